// round 9
// baseline (speedup 1.0000x reference)
#include <cuda_runtime.h>
#include <cuda_bf16.h>
#include <cstdint>

// ---------------------------------------------------------------------------
// Problem constants
// ---------------------------------------------------------------------------
#define BB      2
#define SS      2048
#define HIDDEN  2048
#define NH      8
#define NKV     1
#define HD      256
#define INTER   16384
#define MTOK    (BB*SS)          // 4096 tokens
#define QKVN    (NH*HD + 2*HD)   // 2560 fused QKV output cols
#define KOFF    (NH*HD)          // 2048: k col offset in qkv
#define VOFF    (NH*HD + HD)     // 2304: v col offset in qkv

// ---------------------------------------------------------------------------
// Scratch
// ---------------------------------------------------------------------------
__device__ float g_h   [(size_t)MTOK * HIDDEN];
__device__ float g_wqkv[(size_t)QKVN * HIDDEN];
__device__ float g_qkv [(size_t)MTOK * QKVN];
__device__ float g_vt  [(size_t)BB * HD * SS];
__device__ float g_sc  [(size_t)BB * NH * SS * SS];
__device__ float g_attn[(size_t)MTOK * NH * HD];
__device__ float g_h2  [(size_t)MTOK * HIDDEN];
__device__ float g_h3  [(size_t)MTOK * HIDDEN];
__device__ float g_gate[(size_t)MTOK * INTER];
__device__ float g_up  [(size_t)MTOK * INTER];

// ---------------------------------------------------------------------------
// Helpers
// ---------------------------------------------------------------------------
__device__ __forceinline__ unsigned f2tf(float x) {
    unsigned u;
    asm("cvt.rna.tf32.f32 %0, %1;" : "=r"(u) : "f"(x));
    return u;
}
__device__ __forceinline__ float roundtf(float x) {
    return __uint_as_float(f2tf(x));
}

__device__ __forceinline__ void cp_async16(float* sptr, const float* gptr) {
    unsigned sa = (unsigned)__cvta_generic_to_shared(sptr);
    asm volatile("cp.async.cg.shared.global [%0], [%1], 16;\n"
                 :: "r"(sa), "l"(gptr));
}
__device__ __forceinline__ void cp_commit() {
    asm volatile("cp.async.commit_group;\n");
}
__device__ __forceinline__ void cp_wait2() {
    asm volatile("cp.async.wait_group 2;\n");
}

__device__ __forceinline__ void ldsm4(unsigned& r0, unsigned& r1,
                                      unsigned& r2, unsigned& r3, unsigned sa) {
    asm volatile("ldmatrix.sync.aligned.m8n8.x4.shared.b16 {%0,%1,%2,%3}, [%4];"
                 : "=r"(r0), "=r"(r1), "=r"(r2), "=r"(r3) : "r"(sa));
}

// ---------------------------------------------------------------------------
// TF32 NT GEMM: 256x128x16 CTA tiles, 8 warps of 64x64 (4x2 warp grid),
// 1 CTA/SM, 4-stage cp.async, ldmatrix fragment loads.
// A operands must be pre-rounded to tf32 in gmem.
// CVTB: round B fragments in-loop (raw fp32 weights).
// ROUNDC: round outputs to tf32 (when C feeds a later GEMM as A operand).
// ---------------------------------------------------------------------------
#define GBM 256
#define GBN 128
#define GBK 16
#define GLD 20
#define STAGES 4
#define STAGE_A_F (GBM * GLD)                     // 5120 floats per stage
#define STAGE_B_F (GBN * GLD)                     // 2560 floats per stage
#define GEMM_SMEM (STAGES * (STAGE_A_F + STAGE_B_F) * 4)   // 122880 bytes

extern __shared__ float g_smem[];

template<bool CVTB, bool ROUNDC>
__global__ __launch_bounds__(256, 1) void gemm_tf32_nt(
    const float* __restrict__ A, const float* __restrict__ B,
    float* __restrict__ C, const float* __restrict__ addsrc,
    int K, int lda, int ldb, int ldc,
    long long sAb, long long sAh,
    long long sBb, long long sBh,
    long long sCb, long long sCh,
    int zInner, float alpha)
{
    float* sA = g_smem;                          // STAGES * STAGE_A_F
    float* sB = g_smem + STAGES * STAGE_A_F;     // STAGES * STAGE_B_F

    const int zb = blockIdx.z / zInner;
    const int zh = blockIdx.z % zInner;
    const float* Ab = A + zb * sAb + zh * sAh;
    const float* Bb = B + zb * sBb + zh * sBh;
    float*       Cb = C + zb * sCb + zh * sCh;
    const float* Db = addsrc ? (addsrc + zb * sCb + zh * sCh) : nullptr;

    const int m0  = blockIdx.y * GBM;
    const int n0  = blockIdx.x * GBN;
    const int tid = threadIdx.x;

    // cp.async loaders: A = 4 float4/thread/stage, B = 2 float4/thread/stage
    const int lr = tid >> 2;                  // 0..63
    const int lc = (tid & 3) << 2;            // 0,4,8,12
    const float* Ap0 = Ab + (long long)(m0 + lr) * lda + lc;
    const float* Ap1 = Ab + (long long)(m0 + lr + 64) * lda + lc;
    const float* Ap2 = Ab + (long long)(m0 + lr + 128) * lda + lc;
    const float* Ap3 = Ab + (long long)(m0 + lr + 192) * lda + lc;
    const float* Bp0 = Bb + (long long)(n0 + lr) * ldb + lc;
    const float* Bp1 = Bb + (long long)(n0 + lr + 64) * ldb + lc;
    const int soff0 = lr * GLD + lc;
    const int soff1 = (lr + 64) * GLD + lc;
    const int soff2 = (lr + 128) * GLD + lc;
    const int soff3 = (lr + 192) * GLD + lc;

    const int lane = tid & 31, warp = tid >> 5;
    const int wm = (warp >> 1) * 64;          // 0,64,128,192
    const int wn = (warp & 1) * 64;           // 0,64
    const int g  = lane >> 2, t4 = lane & 3;

    // ldmatrix per-lane addressing
    const int aRow = wm + (lane & 15);
    const int aK   = (lane >> 4) << 2;        // 0 or 4
    const int bRow = wn + (lane & 7) + ((lane >> 4) << 3);
    const int bK   = ((lane >> 3) & 1) << 2;  // 0 or 4

    const unsigned sbase  = (unsigned)__cvta_generic_to_shared(g_smem);
    const unsigned sBbase = sbase + (unsigned)(STAGES * STAGE_A_F) * 4u;

    float acc[4][8][4];
#pragma unroll
    for (int i = 0; i < 4; i++)
#pragma unroll
        for (int j = 0; j < 8; j++)
#pragma unroll
            for (int r = 0; r < 4; r++) acc[i][j][r] = 0.f;

    const int nk = K / GBK;

    // Prologue: issue stages 0..2
#pragma unroll
    for (int s = 0; s < STAGES - 1; ++s) {
        if (s < nk) {
            const int ko = s * GBK;
            cp_async16(&sA[s * STAGE_A_F + soff0], Ap0 + ko);
            cp_async16(&sA[s * STAGE_A_F + soff1], Ap1 + ko);
            cp_async16(&sA[s * STAGE_A_F + soff2], Ap2 + ko);
            cp_async16(&sA[s * STAGE_A_F + soff3], Ap3 + ko);
            cp_async16(&sB[s * STAGE_B_F + soff0], Bp0 + ko);
            cp_async16(&sB[s * STAGE_B_F + soff1], Bp1 + ko);
        }
        cp_commit();
    }
    cp_wait2();
    __syncthreads();

    for (int t = 0; t < nk; ++t) {
        const int s = t & (STAGES - 1);

        const int tf = t + STAGES - 1;
        if (tf < nk) {
            const int sf = tf & (STAGES - 1);
            const int ko = tf * GBK;
            cp_async16(&sA[sf * STAGE_A_F + soff0], Ap0 + ko);
            cp_async16(&sA[sf * STAGE_A_F + soff1], Ap1 + ko);
            cp_async16(&sA[sf * STAGE_A_F + soff2], Ap2 + ko);
            cp_async16(&sA[sf * STAGE_A_F + soff3], Ap3 + ko);
            cp_async16(&sB[sf * STAGE_B_F + soff0], Bp0 + ko);
            cp_async16(&sB[sf * STAGE_B_F + soff1], Bp1 + ko);
        }
        cp_commit();

        const unsigned aSt = sbase  + (unsigned)(s * STAGE_A_F) * 4u;
        const unsigned bSt = sBbase + (unsigned)(s * STAGE_B_F) * 4u;

#pragma unroll
        for (int kk = 0; kk < GBK; kk += 8) {
            unsigned af[4][4];
            unsigned bf[8][2];
#pragma unroll
            for (int mi = 0; mi < 4; mi++) {
                const unsigned addr =
                    aSt + (unsigned)(((aRow + mi * 16) * GLD) + kk + aK) * 4u;
                ldsm4(af[mi][0], af[mi][1], af[mi][2], af[mi][3], addr);
            }
#pragma unroll
            for (int p = 0; p < 4; p++) {
                const unsigned addr =
                    bSt + (unsigned)(((bRow + p * 16) * GLD) + kk + bK) * 4u;
                ldsm4(bf[2 * p][0], bf[2 * p][1], bf[2 * p + 1][0], bf[2 * p + 1][1], addr);
            }
            if (CVTB) {
#pragma unroll
                for (int ni = 0; ni < 8; ni++) {
                    bf[ni][0] = f2tf(__uint_as_float(bf[ni][0]));
                    bf[ni][1] = f2tf(__uint_as_float(bf[ni][1]));
                }
            }
#pragma unroll
            for (int mi = 0; mi < 4; mi++)
#pragma unroll
                for (int ni = 0; ni < 8; ni++)
                    asm volatile(
                        "mma.sync.aligned.m16n8k8.row.col.f32.tf32.tf32.f32 "
                        "{%0,%1,%2,%3},{%4,%5,%6,%7},{%8,%9},{%0,%1,%2,%3};"
                        : "+f"(acc[mi][ni][0]), "+f"(acc[mi][ni][1]),
                          "+f"(acc[mi][ni][2]), "+f"(acc[mi][ni][3])
                        : "r"(af[mi][0]), "r"(af[mi][1]), "r"(af[mi][2]), "r"(af[mi][3]),
                          "r"(bf[ni][0]), "r"(bf[ni][1]));
        }

        cp_wait2();
        __syncthreads();
    }

    // Epilogue
#pragma unroll
    for (int mi = 0; mi < 4; mi++) {
#pragma unroll
        for (int ni = 0; ni < 8; ni++) {
            const int row = m0 + wm + mi * 16 + g;
            const int col = n0 + wn + ni * 8 + 2 * t4;
            const long long o1 = (long long)row * ldc + col;
            const long long o2 = o1 + (long long)8 * ldc;
            float v0 = alpha * acc[mi][ni][0];
            float v1 = alpha * acc[mi][ni][1];
            float v2 = alpha * acc[mi][ni][2];
            float v3 = alpha * acc[mi][ni][3];
            if (Db) {
                v0 += Db[o1]; v1 += Db[o1 + 1];
                v2 += Db[o2]; v3 += Db[o2 + 1];
            }
            if (ROUNDC) {
                v0 = roundtf(v0); v1 = roundtf(v1);
                v2 = roundtf(v2); v3 = roundtf(v3);
            }
            Cb[o1] = v0; Cb[o1 + 1] = v1;
            Cb[o2] = v2; Cb[o2 + 1] = v3;
        }
    }
}

// ---------------------------------------------------------------------------
// RMSNorm (output rounded to tf32 — consumed only as GEMM A operand)
// ---------------------------------------------------------------------------
__global__ __launch_bounds__(256) void rmsnorm_kernel(
    const float* __restrict__ x, const float* __restrict__ w,
    float* __restrict__ o)
{
    const long long row = blockIdx.x;
    const float* xr = x + row * HIDDEN;
    float* orow = o + row * HIDDEN;

    float ss = 0.f;
    for (int i = threadIdx.x; i < HIDDEN; i += 256) {
        const float v = xr[i];
        ss = fmaf(v, v, ss);
    }
#pragma unroll
    for (int off = 16; off; off >>= 1) ss += __shfl_xor_sync(~0u, ss, off);

    __shared__ float sred[8];
    const int wi = threadIdx.x >> 5, li = threadIdx.x & 31;
    if (li == 0) sred[wi] = ss;
    __syncthreads();
    float tot = 0.f;
#pragma unroll
    for (int i = 0; i < 8; i++) tot += sred[i];

    const float rs = rsqrtf(tot * (1.0f / HIDDEN) + 1e-6f);
    for (int i = threadIdx.x; i < HIDDEN; i += 256)
        orow[i] = roundtf(xr[i] * rs * (1.0f + w[i]));
}

// ---------------------------------------------------------------------------
// RoPE (in place, writes tf32-rounded)
// ---------------------------------------------------------------------------
__global__ void rope_kernel(float* __restrict__ x,
                            const float* __restrict__ cs,
                            const float* __restrict__ sn,
                            int nheads, int tok_stride, long long total)
{
    const long long idx = (long long)blockIdx.x * blockDim.x + threadIdx.x;
    if (idx >= total) return;
    const int i = (int)(idx & 127);
    const long long t = idx >> 7;
    const int h = (int)(t % nheads);
    const long long bs = t / nheads;
    const int s = (int)(bs & (SS - 1));
    const float c = cs[s * 128 + i];
    const float si = sn[s * 128 + i];
    float* p = x + bs * tok_stride + h * HD;
    const float x1 = p[i];
    const float x2 = p[i + 128];
    p[i]       = roundtf(x1 * c - x2 * si);
    p[i + 128] = roundtf(x1 * si + x2 * c);
}

// ---------------------------------------------------------------------------
// Transpose V (writes tf32-rounded)
// ---------------------------------------------------------------------------
__global__ void transpose_v_kernel(const float* __restrict__ v,
                                   float* __restrict__ vt)
{
    __shared__ float tile[32][33];
    const int b = blockIdx.z;
    const int c0 = blockIdx.x * 32;
    const int d0 = blockIdx.y * 32;
    const float* vb = v + (long long)b * SS * QKVN;
    float* vtb = vt + (long long)b * HD * SS;
    const int tx = threadIdx.x, ty = threadIdx.y;
    tile[ty][tx] = vb[(long long)(c0 + ty) * QKVN + d0 + tx];
    __syncthreads();
    vtb[(long long)(d0 + ty) * SS + c0 + tx] = roundtf(tile[tx][ty]);
}

// ---------------------------------------------------------------------------
// Causal softmax (writes tf32-rounded probabilities)
// ---------------------------------------------------------------------------
__global__ __launch_bounds__(256) void softmax_causal_kernel(float* __restrict__ sc)
{
    const long long rowid = blockIdx.x;
    const int s = (int)(rowid & (SS - 1));
    float* row = sc + rowid * SS;
    const int n = s + 1;

    float mx = -3.4e38f;
    for (int i = threadIdx.x; i < n; i += 256) mx = fmaxf(mx, row[i]);
#pragma unroll
    for (int off = 16; off; off >>= 1) mx = fmaxf(mx, __shfl_xor_sync(~0u, mx, off));

    __shared__ float sm[8], ssum[8];
    const int wi = threadIdx.x >> 5, li = threadIdx.x & 31;
    if (li == 0) sm[wi] = mx;
    __syncthreads();
    float m2 = -3.4e38f;
#pragma unroll
    for (int i = 0; i < 8; i++) m2 = fmaxf(m2, sm[i]);

    float sum = 0.f;
    for (int i = threadIdx.x; i < n; i += 256) sum += __expf(row[i] - m2);
#pragma unroll
    for (int off = 16; off; off >>= 1) sum += __shfl_xor_sync(~0u, sum, off);
    if (li == 0) ssum[wi] = sum;
    __syncthreads();
    float tot = 0.f;
#pragma unroll
    for (int i = 0; i < 8; i++) tot += ssum[i];
    const float inv = 1.0f / tot;

    for (int i = threadIdx.x; i < SS; i += 256)
        row[i] = (i < n) ? roundtf(__expf(row[i] - m2) * inv) : 0.f;
}

// ---------------------------------------------------------------------------
// gate = gelu_tanh(gate) * up (writes tf32-rounded)
// ---------------------------------------------------------------------------
__global__ void gelumul_kernel(float* __restrict__ gate,
                               const float* __restrict__ up,
                               long long total)
{
    const long long i = (long long)blockIdx.x * blockDim.x + threadIdx.x;
    if (i >= total) return;
    const float x = gate[i];
    const float x3 = x * x * x;
    const float t = tanhf(0.7978845608028654f * (x + 0.044715f * x3));
    gate[i] = roundtf(0.5f * x * (1.0f + t) * up[i]);
}

// ---------------------------------------------------------------------------
// Launch
// ---------------------------------------------------------------------------
extern "C" void kernel_launch(void* const* d_in, const int* in_sizes, int n_in,
                              void* d_out, int out_size)
{
    (void)in_sizes; (void)n_in; (void)out_size;

    const float* hidden = (const float*)d_in[0];
    const float* fcos   = (const float*)d_in[1];
    const float* fsin   = (const float*)d_in[2];
    const float* q_w    = (const float*)d_in[7];
    const float* k_w    = (const float*)d_in[8];
    const float* v_w    = (const float*)d_in[9];
    const float* o_w    = (const float*)d_in[10];
    const float* gate_w = (const float*)d_in[11];
    const float* up_w   = (const float*)d_in[12];
    const float* down_w = (const float*)d_in[13];
    const float* ln1    = (const float*)d_in[14];
    const float* ln2    = (const float*)d_in[15];
    float* out = (float*)d_out;

    float *h, *wqkv, *qkv, *vt, *sc, *attn, *h2, *h3, *gbuf, *ubuf;
    cudaGetSymbolAddress((void**)&h,    g_h);
    cudaGetSymbolAddress((void**)&wqkv, g_wqkv);
    cudaGetSymbolAddress((void**)&qkv,  g_qkv);
    cudaGetSymbolAddress((void**)&vt,   g_vt);
    cudaGetSymbolAddress((void**)&sc,   g_sc);
    cudaGetSymbolAddress((void**)&attn, g_attn);
    cudaGetSymbolAddress((void**)&h2,   g_h2);
    cudaGetSymbolAddress((void**)&h3,   g_h3);
    cudaGetSymbolAddress((void**)&gbuf, g_gate);
    cudaGetSymbolAddress((void**)&ubuf, g_up);

    cudaFuncSetAttribute(gemm_tf32_nt<true,  false>,
                         cudaFuncAttributeMaxDynamicSharedMemorySize, GEMM_SMEM);
    cudaFuncSetAttribute(gemm_tf32_nt<false, false>,
                         cudaFuncAttributeMaxDynamicSharedMemorySize, GEMM_SMEM);
    cudaFuncSetAttribute(gemm_tf32_nt<false, true>,
                         cudaFuncAttributeMaxDynamicSharedMemorySize, GEMM_SMEM);

    const float scaling = 0.0625f;   // HEAD_DIM^-0.5 = 1/16

    // 0) concatenate q/k/v weights into one [2560, 2048] matrix
    cudaMemcpyAsync(wqkv,                         q_w, (size_t)KOFF * HIDDEN * 4,
                    cudaMemcpyDeviceToDevice, 0);
    cudaMemcpyAsync(wqkv + (size_t)KOFF * HIDDEN, k_w, (size_t)HD * HIDDEN * 4,
                    cudaMemcpyDeviceToDevice, 0);
    cudaMemcpyAsync(wqkv + (size_t)VOFF * HIDDEN, v_w, (size_t)HD * HIDDEN * 4,
                    cudaMemcpyDeviceToDevice, 0);

    // 1) rmsnorm(hidden, ln1) -> h (tf32-rounded)
    rmsnorm_kernel<<<MTOK, 256>>>(hidden, ln1, h);

    // 2) fused QKV projection
    gemm_tf32_nt<true, false><<<dim3(QKVN / GBN, MTOK / GBM, 1), 256, GEMM_SMEM>>>(
        h, wqkv, qkv, nullptr, HIDDEN, HIDDEN, HIDDEN, QKVN,
        0, 0, 0, 0, 0, 0, 1, 1.0f);

    // 3) RoPE on q and k (rounds in place)
    {
        const long long tq = (long long)MTOK * NH * 128;
        rope_kernel<<<(unsigned)((tq + 255) / 256), 256>>>(
            qkv, fcos, fsin, NH, QKVN, tq);
        const long long tk = (long long)MTOK * 128;
        rope_kernel<<<(unsigned)((tk + 255) / 256), 256>>>(
            qkv + KOFF, fcos, fsin, 1, QKVN, tk);
    }

    // 4) transpose V -> vt (rounds)
    transpose_v_kernel<<<dim3(SS / 32, HD / 32, BB), dim3(32, 32)>>>(
        qkv + VOFF, vt);

    // 5) scores = (q . k^T) * scaling (both operands pre-rounded)
    gemm_tf32_nt<false, false><<<dim3(SS / GBN, SS / GBM, BB * NH), 256, GEMM_SMEM>>>(
        qkv, qkv + KOFF, sc, nullptr, HD,
        QKVN, QKVN, SS,
        (long long)SS * QKVN, (long long)HD,
        (long long)SS * QKVN, 0,
        (long long)NH * SS * SS, (long long)SS * SS,
        NH, scaling);

    // 6) causal softmax (rounds probs)
    softmax_causal_kernel<<<BB * NH * SS, 256>>>(sc);

    // 7) attn = probs . v (pre-rounded inputs; round output for O-proj)
    gemm_tf32_nt<false, true><<<dim3(HD / GBN, SS / GBM, BB * NH), 256, GEMM_SMEM>>>(
        sc, vt, attn, nullptr, SS,
        SS, SS, NH * HD,
        (long long)NH * SS * SS, (long long)SS * SS,
        (long long)HD * SS, 0,
        (long long)SS * NH * HD, (long long)HD,
        NH, 1.0f);

    // 8) h2 = hidden + attn . o_w^T
    gemm_tf32_nt<true, false><<<dim3(HIDDEN / GBN, MTOK / GBM, 1), 256, GEMM_SMEM>>>(
        attn, o_w, h2, hidden, NH * HD, NH * HD, NH * HD, HIDDEN,
        0, 0, 0, 0, 0, 0, 1, 1.0f);

    // 9) rmsnorm(h2, ln2) -> h3 (rounded)
    rmsnorm_kernel<<<MTOK, 256>>>(h2, ln2, h3);

    // 10-11) gate / up projections
    gemm_tf32_nt<true, false><<<dim3(INTER / GBN, MTOK / GBM, 1), 256, GEMM_SMEM>>>(
        h3, gate_w, gbuf, nullptr, HIDDEN, HIDDEN, HIDDEN, INTER,
        0, 0, 0, 0, 0, 0, 1, 1.0f);
    gemm_tf32_nt<true, false><<<dim3(INTER / GBN, MTOK / GBM, 1), 256, GEMM_SMEM>>>(
        h3, up_w, ubuf, nullptr, HIDDEN, HIDDEN, HIDDEN, INTER,
        0, 0, 0, 0, 0, 0, 1, 1.0f);

    // 12) gbuf = gelu(gbuf) * ubuf (rounded)
    {
        const long long tot = (long long)MTOK * INTER;
        gelumul_kernel<<<(unsigned)((tot + 255) / 256), 256>>>(gbuf, ubuf, tot);
    }

    // 13) out = h2 + gbuf . down_w^T
    gemm_tf32_nt<true, false><<<dim3(HIDDEN / GBN, MTOK / GBM, 1), 256, GEMM_SMEM>>>(
        gbuf, down_w, out, h2, INTER, INTER, INTER, HIDDEN,
        0, 0, 0, 0, 0, 0, 1, 1.0f);
}

// round 10
// speedup vs baseline: 1.0992x; 1.0992x over previous
#include <cuda_runtime.h>
#include <cuda_bf16.h>
#include <cstdint>

// ---------------------------------------------------------------------------
// Problem constants
// ---------------------------------------------------------------------------
#define BB      2
#define SS      2048
#define HIDDEN  2048
#define NH      8
#define NKV     1
#define HD      256
#define INTER   16384
#define MTOK    (BB*SS)          // 4096 tokens
#define QKVN    (NH*HD + 2*HD)   // 2560 fused QKV output cols
#define KOFF    (NH*HD)          // 2048: k col offset in qkv
#define VOFF    (NH*HD + HD)     // 2304: v col offset in qkv

// ---------------------------------------------------------------------------
// Scratch
// ---------------------------------------------------------------------------
__device__ float g_h   [(size_t)MTOK * HIDDEN];
__device__ float g_wqkv[(size_t)QKVN * HIDDEN];
__device__ float g_qkv [(size_t)MTOK * QKVN];
__device__ float g_vt  [(size_t)BB * HD * SS];
__device__ float g_sc  [(size_t)BB * NH * SS * SS];
__device__ float g_attn[(size_t)MTOK * NH * HD];
__device__ float g_h2  [(size_t)MTOK * HIDDEN];
__device__ float g_h3  [(size_t)MTOK * HIDDEN];
__device__ float g_gate[(size_t)MTOK * INTER];
__device__ float g_up  [(size_t)MTOK * INTER];

// ---------------------------------------------------------------------------
// Helpers
// ---------------------------------------------------------------------------
__device__ __forceinline__ unsigned f2tf(float x) {
    unsigned u;
    asm("cvt.rna.tf32.f32 %0, %1;" : "=r"(u) : "f"(x));
    return u;
}
__device__ __forceinline__ float roundtf(float x) {
    return __uint_as_float(f2tf(x));
}

__device__ __forceinline__ void cp_async16(float* sptr, const float* gptr) {
    unsigned sa = (unsigned)__cvta_generic_to_shared(sptr);
    asm volatile("cp.async.cg.shared.global [%0], [%1], 16;\n"
                 :: "r"(sa), "l"(gptr));
}
__device__ __forceinline__ void cp_commit() {
    asm volatile("cp.async.commit_group;\n");
}
__device__ __forceinline__ void cp_wait2() {
    asm volatile("cp.async.wait_group 2;\n");
}

__device__ __forceinline__ void ldsm4(unsigned& r0, unsigned& r1,
                                      unsigned& r2, unsigned& r3, unsigned sa) {
    asm volatile("ldmatrix.sync.aligned.m8n8.x4.shared.b16 {%0,%1,%2,%3}, [%4];"
                 : "=r"(r0), "=r"(r1), "=r"(r2), "=r"(r3) : "r"(sa));
}

// ---------------------------------------------------------------------------
// TF32 NT GEMM: 128x128x16 CTA tiles, 4 warps of 64x64 (2x2 warp grid),
// 128 threads, 2 CTAs/SM, 4-stage cp.async, ldmatrix fragment loads.
// A operands must be pre-rounded to tf32 in gmem.
// CVTB: round B fragments in-loop (raw fp32 weights).
// ROUNDC: round outputs to tf32 (when C feeds a later GEMM as A operand).
// ---------------------------------------------------------------------------
#define GBM 128
#define GBN 128
#define GBK 16
#define GLD 20
#define STAGES 4
#define STAGE_F (GBM * GLD)                       // 2560 floats per mat/stage
#define GEMM_SMEM (STAGES * 2 * STAGE_F * 4)      // 81920 bytes

extern __shared__ float g_smem[];

template<bool CVTB, bool ROUNDC>
__global__ __launch_bounds__(128, 2) void gemm_tf32_nt(
    const float* __restrict__ A, const float* __restrict__ B,
    float* __restrict__ C, const float* __restrict__ addsrc,
    int K, int lda, int ldb, int ldc,
    long long sAb, long long sAh,
    long long sBb, long long sBh,
    long long sCb, long long sCh,
    int zInner, float alpha)
{
    float* sA = g_smem;                          // STAGES * STAGE_F
    float* sB = g_smem + STAGES * STAGE_F;

    const int zb = blockIdx.z / zInner;
    const int zh = blockIdx.z % zInner;
    const float* Ab = A + zb * sAb + zh * sAh;
    const float* Bb = B + zb * sBb + zh * sBh;
    float*       Cb = C + zb * sCb + zh * sCh;
    const float* Db = addsrc ? (addsrc + zb * sCb + zh * sCh) : nullptr;

    const int m0  = blockIdx.y * GBM;
    const int n0  = blockIdx.x * GBN;
    const int tid = threadIdx.x;

    // cp.async loaders: 128 threads, 4 float4 per thread per matrix per stage
    const int lr = tid >> 2;                  // 0..31
    const int lc = (tid & 3) << 2;            // 0,4,8,12
    const float* Ap0 = Ab + (long long)(m0 + lr) * lda + lc;
    const float* Ap1 = Ab + (long long)(m0 + lr + 32) * lda + lc;
    const float* Ap2 = Ab + (long long)(m0 + lr + 64) * lda + lc;
    const float* Ap3 = Ab + (long long)(m0 + lr + 96) * lda + lc;
    const float* Bp0 = Bb + (long long)(n0 + lr) * ldb + lc;
    const float* Bp1 = Bb + (long long)(n0 + lr + 32) * ldb + lc;
    const float* Bp2 = Bb + (long long)(n0 + lr + 64) * ldb + lc;
    const float* Bp3 = Bb + (long long)(n0 + lr + 96) * ldb + lc;
    const int soff0 = lr * GLD + lc;
    const int soff1 = (lr + 32) * GLD + lc;
    const int soff2 = (lr + 64) * GLD + lc;
    const int soff3 = (lr + 96) * GLD + lc;

    const int lane = tid & 31, warp = tid >> 5;   // warps 0..3
    const int wm = (warp >> 1) * 64;          // 0 / 64
    const int wn = (warp & 1) * 64;           // 0 / 64
    const int g  = lane >> 2, t4 = lane & 3;

    // ldmatrix per-lane addressing
    const int aRow = wm + (lane & 15);
    const int aK   = (lane >> 4) << 2;        // 0 or 4
    const int bRow = wn + (lane & 7) + ((lane >> 4) << 3);
    const int bK   = ((lane >> 3) & 1) << 2;  // 0 or 4

    const unsigned sbase  = (unsigned)__cvta_generic_to_shared(g_smem);
    const unsigned sBbase = sbase + (unsigned)(STAGES * STAGE_F) * 4u;

    float acc[4][8][4];
#pragma unroll
    for (int i = 0; i < 4; i++)
#pragma unroll
        for (int j = 0; j < 8; j++)
#pragma unroll
            for (int r = 0; r < 4; r++) acc[i][j][r] = 0.f;

    const int nk = K / GBK;

    // Prologue: issue stages 0..2
#pragma unroll
    for (int s = 0; s < STAGES - 1; ++s) {
        if (s < nk) {
            const int ko = s * GBK;
            cp_async16(&sA[s * STAGE_F + soff0], Ap0 + ko);
            cp_async16(&sA[s * STAGE_F + soff1], Ap1 + ko);
            cp_async16(&sA[s * STAGE_F + soff2], Ap2 + ko);
            cp_async16(&sA[s * STAGE_F + soff3], Ap3 + ko);
            cp_async16(&sB[s * STAGE_F + soff0], Bp0 + ko);
            cp_async16(&sB[s * STAGE_F + soff1], Bp1 + ko);
            cp_async16(&sB[s * STAGE_F + soff2], Bp2 + ko);
            cp_async16(&sB[s * STAGE_F + soff3], Bp3 + ko);
        }
        cp_commit();
    }
    cp_wait2();
    __syncthreads();

    for (int t = 0; t < nk; ++t) {
        const int s = t & (STAGES - 1);

        const int tf = t + STAGES - 1;
        if (tf < nk) {
            const int sf = tf & (STAGES - 1);
            const int ko = tf * GBK;
            cp_async16(&sA[sf * STAGE_F + soff0], Ap0 + ko);
            cp_async16(&sA[sf * STAGE_F + soff1], Ap1 + ko);
            cp_async16(&sA[sf * STAGE_F + soff2], Ap2 + ko);
            cp_async16(&sA[sf * STAGE_F + soff3], Ap3 + ko);
            cp_async16(&sB[sf * STAGE_F + soff0], Bp0 + ko);
            cp_async16(&sB[sf * STAGE_F + soff1], Bp1 + ko);
            cp_async16(&sB[sf * STAGE_F + soff2], Bp2 + ko);
            cp_async16(&sB[sf * STAGE_F + soff3], Bp3 + ko);
        }
        cp_commit();

        const unsigned aSt = sbase  + (unsigned)(s * STAGE_F) * 4u;
        const unsigned bSt = sBbase + (unsigned)(s * STAGE_F) * 4u;

#pragma unroll
        for (int kk = 0; kk < GBK; kk += 8) {
            unsigned af[4][4];
            unsigned bf[8][2];
#pragma unroll
            for (int mi = 0; mi < 4; mi++) {
                const unsigned addr =
                    aSt + (unsigned)(((aRow + mi * 16) * GLD) + kk + aK) * 4u;
                ldsm4(af[mi][0], af[mi][1], af[mi][2], af[mi][3], addr);
            }
#pragma unroll
            for (int p = 0; p < 4; p++) {
                const unsigned addr =
                    bSt + (unsigned)(((bRow + p * 16) * GLD) + kk + bK) * 4u;
                ldsm4(bf[2 * p][0], bf[2 * p][1], bf[2 * p + 1][0], bf[2 * p + 1][1], addr);
            }
            if (CVTB) {
#pragma unroll
                for (int ni = 0; ni < 8; ni++) {
                    bf[ni][0] = f2tf(__uint_as_float(bf[ni][0]));
                    bf[ni][1] = f2tf(__uint_as_float(bf[ni][1]));
                }
            }
#pragma unroll
            for (int mi = 0; mi < 4; mi++)
#pragma unroll
                for (int ni = 0; ni < 8; ni++)
                    asm volatile(
                        "mma.sync.aligned.m16n8k8.row.col.f32.tf32.tf32.f32 "
                        "{%0,%1,%2,%3},{%4,%5,%6,%7},{%8,%9},{%0,%1,%2,%3};"
                        : "+f"(acc[mi][ni][0]), "+f"(acc[mi][ni][1]),
                          "+f"(acc[mi][ni][2]), "+f"(acc[mi][ni][3])
                        : "r"(af[mi][0]), "r"(af[mi][1]), "r"(af[mi][2]), "r"(af[mi][3]),
                          "r"(bf[ni][0]), "r"(bf[ni][1]));
        }

        cp_wait2();
        __syncthreads();
    }

    // Epilogue
#pragma unroll
    for (int mi = 0; mi < 4; mi++) {
#pragma unroll
        for (int ni = 0; ni < 8; ni++) {
            const int row = m0 + wm + mi * 16 + g;
            const int col = n0 + wn + ni * 8 + 2 * t4;
            const long long o1 = (long long)row * ldc + col;
            const long long o2 = o1 + (long long)8 * ldc;
            float v0 = alpha * acc[mi][ni][0];
            float v1 = alpha * acc[mi][ni][1];
            float v2 = alpha * acc[mi][ni][2];
            float v3 = alpha * acc[mi][ni][3];
            if (Db) {
                v0 += Db[o1]; v1 += Db[o1 + 1];
                v2 += Db[o2]; v3 += Db[o2 + 1];
            }
            if (ROUNDC) {
                v0 = roundtf(v0); v1 = roundtf(v1);
                v2 = roundtf(v2); v3 = roundtf(v3);
            }
            Cb[o1] = v0; Cb[o1 + 1] = v1;
            Cb[o2] = v2; Cb[o2 + 1] = v3;
        }
    }
}

// ---------------------------------------------------------------------------
// RMSNorm (output rounded to tf32 — consumed only as GEMM A operand)
// ---------------------------------------------------------------------------
__global__ __launch_bounds__(256) void rmsnorm_kernel(
    const float* __restrict__ x, const float* __restrict__ w,
    float* __restrict__ o)
{
    const long long row = blockIdx.x;
    const float* xr = x + row * HIDDEN;
    float* orow = o + row * HIDDEN;

    float ss = 0.f;
    for (int i = threadIdx.x; i < HIDDEN; i += 256) {
        const float v = xr[i];
        ss = fmaf(v, v, ss);
    }
#pragma unroll
    for (int off = 16; off; off >>= 1) ss += __shfl_xor_sync(~0u, ss, off);

    __shared__ float sred[8];
    const int wi = threadIdx.x >> 5, li = threadIdx.x & 31;
    if (li == 0) sred[wi] = ss;
    __syncthreads();
    float tot = 0.f;
#pragma unroll
    for (int i = 0; i < 8; i++) tot += sred[i];

    const float rs = rsqrtf(tot * (1.0f / HIDDEN) + 1e-6f);
    for (int i = threadIdx.x; i < HIDDEN; i += 256)
        orow[i] = roundtf(xr[i] * rs * (1.0f + w[i]));
}

// ---------------------------------------------------------------------------
// RoPE (in place, writes tf32-rounded)
// ---------------------------------------------------------------------------
__global__ void rope_kernel(float* __restrict__ x,
                            const float* __restrict__ cs,
                            const float* __restrict__ sn,
                            int nheads, int tok_stride, long long total)
{
    const long long idx = (long long)blockIdx.x * blockDim.x + threadIdx.x;
    if (idx >= total) return;
    const int i = (int)(idx & 127);
    const long long t = idx >> 7;
    const int h = (int)(t % nheads);
    const long long bs = t / nheads;
    const int s = (int)(bs & (SS - 1));
    const float c = cs[s * 128 + i];
    const float si = sn[s * 128 + i];
    float* p = x + bs * tok_stride + h * HD;
    const float x1 = p[i];
    const float x2 = p[i + 128];
    p[i]       = roundtf(x1 * c - x2 * si);
    p[i + 128] = roundtf(x1 * si + x2 * c);
}

// ---------------------------------------------------------------------------
// Transpose V (writes tf32-rounded)
// ---------------------------------------------------------------------------
__global__ void transpose_v_kernel(const float* __restrict__ v,
                                   float* __restrict__ vt)
{
    __shared__ float tile[32][33];
    const int b = blockIdx.z;
    const int c0 = blockIdx.x * 32;
    const int d0 = blockIdx.y * 32;
    const float* vb = v + (long long)b * SS * QKVN;
    float* vtb = vt + (long long)b * HD * SS;
    const int tx = threadIdx.x, ty = threadIdx.y;
    tile[ty][tx] = vb[(long long)(c0 + ty) * QKVN + d0 + tx];
    __syncthreads();
    vtb[(long long)(d0 + ty) * SS + c0 + tx] = roundtf(tile[tx][ty]);
}

// ---------------------------------------------------------------------------
// Causal softmax (writes tf32-rounded probabilities)
// ---------------------------------------------------------------------------
__global__ __launch_bounds__(256) void softmax_causal_kernel(float* __restrict__ sc)
{
    const long long rowid = blockIdx.x;
    const int s = (int)(rowid & (SS - 1));
    float* row = sc + rowid * SS;
    const int n = s + 1;

    float mx = -3.4e38f;
    for (int i = threadIdx.x; i < n; i += 256) mx = fmaxf(mx, row[i]);
#pragma unroll
    for (int off = 16; off; off >>= 1) mx = fmaxf(mx, __shfl_xor_sync(~0u, mx, off));

    __shared__ float sm[8], ssum[8];
    const int wi = threadIdx.x >> 5, li = threadIdx.x & 31;
    if (li == 0) sm[wi] = mx;
    __syncthreads();
    float m2 = -3.4e38f;
#pragma unroll
    for (int i = 0; i < 8; i++) m2 = fmaxf(m2, sm[i]);

    float sum = 0.f;
    for (int i = threadIdx.x; i < n; i += 256) sum += __expf(row[i] - m2);
#pragma unroll
    for (int off = 16; off; off >>= 1) sum += __shfl_xor_sync(~0u, sum, off);
    if (li == 0) ssum[wi] = sum;
    __syncthreads();
    float tot = 0.f;
#pragma unroll
    for (int i = 0; i < 8; i++) tot += ssum[i];
    const float inv = 1.0f / tot;

    for (int i = threadIdx.x; i < SS; i += 256)
        row[i] = (i < n) ? roundtf(__expf(row[i] - m2) * inv) : 0.f;
}

// ---------------------------------------------------------------------------
// gate = gelu_tanh(gate) * up (writes tf32-rounded)
// ---------------------------------------------------------------------------
__global__ void gelumul_kernel(float* __restrict__ gate,
                               const float* __restrict__ up,
                               long long total)
{
    const long long i = (long long)blockIdx.x * blockDim.x + threadIdx.x;
    if (i >= total) return;
    const float x = gate[i];
    const float x3 = x * x * x;
    const float t = tanhf(0.7978845608028654f * (x + 0.044715f * x3));
    gate[i] = roundtf(0.5f * x * (1.0f + t) * up[i]);
}

// ---------------------------------------------------------------------------
// Launch
// ---------------------------------------------------------------------------
extern "C" void kernel_launch(void* const* d_in, const int* in_sizes, int n_in,
                              void* d_out, int out_size)
{
    (void)in_sizes; (void)n_in; (void)out_size;

    const float* hidden = (const float*)d_in[0];
    const float* fcos   = (const float*)d_in[1];
    const float* fsin   = (const float*)d_in[2];
    const float* q_w    = (const float*)d_in[7];
    const float* k_w    = (const float*)d_in[8];
    const float* v_w    = (const float*)d_in[9];
    const float* o_w    = (const float*)d_in[10];
    const float* gate_w = (const float*)d_in[11];
    const float* up_w   = (const float*)d_in[12];
    const float* down_w = (const float*)d_in[13];
    const float* ln1    = (const float*)d_in[14];
    const float* ln2    = (const float*)d_in[15];
    float* out = (float*)d_out;

    float *h, *wqkv, *qkv, *vt, *sc, *attn, *h2, *h3, *gbuf, *ubuf;
    cudaGetSymbolAddress((void**)&h,    g_h);
    cudaGetSymbolAddress((void**)&wqkv, g_wqkv);
    cudaGetSymbolAddress((void**)&qkv,  g_qkv);
    cudaGetSymbolAddress((void**)&vt,   g_vt);
    cudaGetSymbolAddress((void**)&sc,   g_sc);
    cudaGetSymbolAddress((void**)&attn, g_attn);
    cudaGetSymbolAddress((void**)&h2,   g_h2);
    cudaGetSymbolAddress((void**)&h3,   g_h3);
    cudaGetSymbolAddress((void**)&gbuf, g_gate);
    cudaGetSymbolAddress((void**)&ubuf, g_up);

    cudaFuncSetAttribute(gemm_tf32_nt<true,  false>,
                         cudaFuncAttributeMaxDynamicSharedMemorySize, GEMM_SMEM);
    cudaFuncSetAttribute(gemm_tf32_nt<false, false>,
                         cudaFuncAttributeMaxDynamicSharedMemorySize, GEMM_SMEM);
    cudaFuncSetAttribute(gemm_tf32_nt<false, true>,
                         cudaFuncAttributeMaxDynamicSharedMemorySize, GEMM_SMEM);

    const float scaling = 0.0625f;   // HEAD_DIM^-0.5 = 1/16

    // 0) concatenate q/k/v weights into one [2560, 2048] matrix
    cudaMemcpyAsync(wqkv,                         q_w, (size_t)KOFF * HIDDEN * 4,
                    cudaMemcpyDeviceToDevice, 0);
    cudaMemcpyAsync(wqkv + (size_t)KOFF * HIDDEN, k_w, (size_t)HD * HIDDEN * 4,
                    cudaMemcpyDeviceToDevice, 0);
    cudaMemcpyAsync(wqkv + (size_t)VOFF * HIDDEN, v_w, (size_t)HD * HIDDEN * 4,
                    cudaMemcpyDeviceToDevice, 0);

    // 1) rmsnorm(hidden, ln1) -> h (tf32-rounded)
    rmsnorm_kernel<<<MTOK, 256>>>(hidden, ln1, h);

    // 2) fused QKV projection
    gemm_tf32_nt<true, false><<<dim3(QKVN / GBN, MTOK / GBM, 1), 128, GEMM_SMEM>>>(
        h, wqkv, qkv, nullptr, HIDDEN, HIDDEN, HIDDEN, QKVN,
        0, 0, 0, 0, 0, 0, 1, 1.0f);

    // 3) RoPE on q and k (rounds in place)
    {
        const long long tq = (long long)MTOK * NH * 128;
        rope_kernel<<<(unsigned)((tq + 255) / 256), 256>>>(
            qkv, fcos, fsin, NH, QKVN, tq);
        const long long tk = (long long)MTOK * 128;
        rope_kernel<<<(unsigned)((tk + 255) / 256), 256>>>(
            qkv + KOFF, fcos, fsin, 1, QKVN, tk);
    }

    // 4) transpose V -> vt (rounds)
    transpose_v_kernel<<<dim3(SS / 32, HD / 32, BB), dim3(32, 32)>>>(
        qkv + VOFF, vt);

    // 5) scores = (q . k^T) * scaling (both operands pre-rounded)
    gemm_tf32_nt<false, false><<<dim3(SS / GBN, SS / GBM, BB * NH), 128, GEMM_SMEM>>>(
        qkv, qkv + KOFF, sc, nullptr, HD,
        QKVN, QKVN, SS,
        (long long)SS * QKVN, (long long)HD,
        (long long)SS * QKVN, 0,
        (long long)NH * SS * SS, (long long)SS * SS,
        NH, scaling);

    // 6) causal softmax (rounds probs)
    softmax_causal_kernel<<<BB * NH * SS, 256>>>(sc);

    // 7) attn = probs . v (pre-rounded inputs; round output for O-proj)
    gemm_tf32_nt<false, true><<<dim3(HD / GBN, SS / GBM, BB * NH), 128, GEMM_SMEM>>>(
        sc, vt, attn, nullptr, SS,
        SS, SS, NH * HD,
        (long long)NH * SS * SS, (long long)SS * SS,
        (long long)HD * SS, 0,
        (long long)SS * NH * HD, (long long)HD,
        NH, 1.0f);

    // 8) h2 = hidden + attn . o_w^T
    gemm_tf32_nt<true, false><<<dim3(HIDDEN / GBN, MTOK / GBM, 1), 128, GEMM_SMEM>>>(
        attn, o_w, h2, hidden, NH * HD, NH * HD, NH * HD, HIDDEN,
        0, 0, 0, 0, 0, 0, 1, 1.0f);

    // 9) rmsnorm(h2, ln2) -> h3 (rounded)
    rmsnorm_kernel<<<MTOK, 256>>>(h2, ln2, h3);

    // 10-11) gate / up projections
    gemm_tf32_nt<true, false><<<dim3(INTER / GBN, MTOK / GBM, 1), 128, GEMM_SMEM>>>(
        h3, gate_w, gbuf, nullptr, HIDDEN, HIDDEN, HIDDEN, INTER,
        0, 0, 0, 0, 0, 0, 1, 1.0f);
    gemm_tf32_nt<true, false><<<dim3(INTER / GBN, MTOK / GBM, 1), 128, GEMM_SMEM>>>(
        h3, up_w, ubuf, nullptr, HIDDEN, HIDDEN, HIDDEN, INTER,
        0, 0, 0, 0, 0, 0, 1, 1.0f);

    // 12) gbuf = gelu(gbuf) * ubuf (rounded)
    {
        const long long tot = (long long)MTOK * INTER;
        gelumul_kernel<<<(unsigned)((tot + 255) / 256), 256>>>(gbuf, ubuf, tot);
    }

    // 13) out = h2 + gbuf . down_w^T
    gemm_tf32_nt<true, false><<<dim3(HIDDEN / GBN, MTOK / GBM, 1), 128, GEMM_SMEM>>>(
        gbuf, down_w, out, h2, INTER, INTER, INTER, HIDDEN,
        0, 0, 0, 0, 0, 0, 1, 1.0f);
}

// round 11
// speedup vs baseline: 1.2194x; 1.1094x over previous
#include <cuda_runtime.h>
#include <cuda_bf16.h>
#include <cstdint>

// ---------------------------------------------------------------------------
// Problem constants
// ---------------------------------------------------------------------------
#define BB      2
#define SS      2048
#define HIDDEN  2048
#define NH      8
#define NKV     1
#define HD      256
#define INTER   16384
#define MTOK    (BB*SS)          // 4096 tokens
#define QKVN    (NH*HD + 2*HD)   // 2560 fused QKV output cols
#define KOFF    (NH*HD)          // 2048: k col offset in qkv
#define VOFF    (NH*HD + HD)     // 2304: v col offset in qkv

// ---------------------------------------------------------------------------
// Scratch
// ---------------------------------------------------------------------------
__device__ float g_h   [(size_t)MTOK * HIDDEN];
__device__ float g_wqkv[(size_t)QKVN * HIDDEN];
__device__ float g_qkv [(size_t)MTOK * QKVN];
__device__ float g_vt  [(size_t)BB * HD * SS];
__device__ float g_sc  [(size_t)BB * NH * SS * SS];
__device__ float g_attn[(size_t)MTOK * NH * HD];
__device__ float g_h2  [(size_t)MTOK * HIDDEN];
__device__ float g_h3  [(size_t)MTOK * HIDDEN];
__device__ float g_gate[(size_t)MTOK * INTER];
__device__ float g_up  [(size_t)MTOK * INTER];

// ---------------------------------------------------------------------------
// Helpers
// ---------------------------------------------------------------------------
__device__ __forceinline__ unsigned f2tf(float x) {
    unsigned u;
    asm("cvt.rna.tf32.f32 %0, %1;" : "=r"(u) : "f"(x));
    return u;
}
__device__ __forceinline__ float roundtf(float x) {
    return __uint_as_float(f2tf(x));
}

__device__ __forceinline__ void cp_async16(float* sptr, const float* gptr) {
    unsigned sa = (unsigned)__cvta_generic_to_shared(sptr);
    asm volatile("cp.async.cg.shared.global [%0], [%1], 16;\n"
                 :: "r"(sa), "l"(gptr));
}
__device__ __forceinline__ void cp_commit() {
    asm volatile("cp.async.commit_group;\n");
}
__device__ __forceinline__ void cp_wait2() {
    asm volatile("cp.async.wait_group 2;\n");
}

__device__ __forceinline__ void ldsm4(unsigned& r0, unsigned& r1,
                                      unsigned& r2, unsigned& r3, unsigned sa) {
    asm volatile("ldmatrix.sync.aligned.m8n8.x4.shared.b16 {%0,%1,%2,%3}, [%4];"
                 : "=r"(r0), "=r"(r1), "=r"(r2), "=r"(r3) : "r"(sa));
}

// ---------------------------------------------------------------------------
// TF32 NT GEMM: 128x128x16 tiles, 8 warps (64x32 warp tiles), 256 threads,
// 2 CTAs/SM, 4-stage cp.async, ldmatrix fragment loads.  (= R8 baseline)
// A operands must be pre-rounded to tf32 in gmem.
// CVTB: round B fragments in-loop (raw fp32 weights).
// ROUNDC: round outputs to tf32 (when C feeds a later GEMM as A operand).
// causal_skip: early-return blocks with n0 >= m0+GBM (fully masked scores).
// klim: truncate K loop to m0+GBM (exact for causal probs: zeros beyond).
// ---------------------------------------------------------------------------
#define GBM 128
#define GBN 128
#define GBK 16
#define GLD 20
#define STAGES 4
#define STAGE_F (GBM * GLD)                       // 2560 floats per mat/stage
#define GEMM_SMEM (STAGES * 2 * STAGE_F * 4)      // 81920 bytes

extern __shared__ float g_smem[];

template<bool CVTB, bool ROUNDC>
__global__ __launch_bounds__(256, 2) void gemm_tf32_nt(
    const float* __restrict__ A, const float* __restrict__ B,
    float* __restrict__ C, const float* __restrict__ addsrc,
    int K, int lda, int ldb, int ldc,
    long long sAb, long long sAh,
    long long sBb, long long sBh,
    long long sCb, long long sCh,
    int zInner, float alpha, int causal_skip, int klim)
{
    const int m0  = blockIdx.y * GBM;
    const int n0  = blockIdx.x * GBN;
    if (causal_skip && n0 >= m0 + GBM) return;   // fully-masked scores block

    int Keff = K;
    if (klim && (m0 + GBM) < Keff) Keff = m0 + GBM;  // probs zero beyond row

    float* sA = g_smem;
    float* sB = g_smem + STAGES * STAGE_F;

    const int zb = blockIdx.z / zInner;
    const int zh = blockIdx.z % zInner;
    const float* Ab = A + zb * sAb + zh * sAh;
    const float* Bb = B + zb * sBb + zh * sBh;
    float*       Cb = C + zb * sCb + zh * sCh;
    const float* Db = addsrc ? (addsrc + zb * sCb + zh * sCh) : nullptr;

    const int tid = threadIdx.x;

    // cp.async loader mapping: 1 float4 per thread per half-matrix per stage
    const int lr = tid >> 2;                  // 0..63
    const int lc = (tid & 3) << 2;            // 0,4,8,12
    const float* Ap0 = Ab + (long long)(m0 + lr) * lda + lc;
    const float* Ap1 = Ab + (long long)(m0 + lr + 64) * lda + lc;
    const float* Bp0 = Bb + (long long)(n0 + lr) * ldb + lc;
    const float* Bp1 = Bb + (long long)(n0 + lr + 64) * ldb + lc;
    const int soff0 = lr * GLD + lc;
    const int soff1 = (lr + 64) * GLD + lc;

    const int lane = tid & 31, warp = tid >> 5;
    const int wm = (warp >> 2) * 64;          // 0 / 64
    const int wn = (warp & 3) * 32;           // 0..96
    const int g  = lane >> 2, t4 = lane & 3;

    // ldmatrix per-lane addressing
    const int aRow = wm + (lane & 15);
    const int aK   = (lane >> 4) << 2;        // 0 or 4
    const int bRow = wn + (lane & 7) + ((lane >> 4) << 3);
    const int bK   = ((lane >> 3) & 1) << 2;  // 0 or 4

    const unsigned sbase  = (unsigned)__cvta_generic_to_shared(g_smem);
    const unsigned sBbase = sbase + (unsigned)(STAGES * STAGE_F) * 4u;

    float acc[4][4][4];
#pragma unroll
    for (int i = 0; i < 4; i++)
#pragma unroll
        for (int j = 0; j < 4; j++)
#pragma unroll
            for (int r = 0; r < 4; r++) acc[i][j][r] = 0.f;

    const int nk = Keff / GBK;

    // Prologue: issue stages 0..2
#pragma unroll
    for (int s = 0; s < STAGES - 1; ++s) {
        if (s < nk) {
            const int ko = s * GBK;
            cp_async16(&sA[s * STAGE_F + soff0], Ap0 + ko);
            cp_async16(&sA[s * STAGE_F + soff1], Ap1 + ko);
            cp_async16(&sB[s * STAGE_F + soff0], Bp0 + ko);
            cp_async16(&sB[s * STAGE_F + soff1], Bp1 + ko);
        }
        cp_commit();
    }
    cp_wait2();
    __syncthreads();

    for (int t = 0; t < nk; ++t) {
        const int s = t & (STAGES - 1);

        const int tf = t + STAGES - 1;
        if (tf < nk) {
            const int sf = tf & (STAGES - 1);
            const int ko = tf * GBK;
            cp_async16(&sA[sf * STAGE_F + soff0], Ap0 + ko);
            cp_async16(&sA[sf * STAGE_F + soff1], Ap1 + ko);
            cp_async16(&sB[sf * STAGE_F + soff0], Bp0 + ko);
            cp_async16(&sB[sf * STAGE_F + soff1], Bp1 + ko);
        }
        cp_commit();

        const unsigned aSt = sbase  + (unsigned)(s * STAGE_F) * 4u;
        const unsigned bSt = sBbase + (unsigned)(s * STAGE_F) * 4u;

#pragma unroll
        for (int kk = 0; kk < GBK; kk += 8) {
            unsigned af[4][4];
            unsigned bf[4][2];
#pragma unroll
            for (int mi = 0; mi < 4; mi++) {
                const unsigned addr =
                    aSt + (unsigned)(((aRow + mi * 16) * GLD) + kk + aK) * 4u;
                ldsm4(af[mi][0], af[mi][1], af[mi][2], af[mi][3], addr);
            }
#pragma unroll
            for (int p = 0; p < 2; p++) {
                const unsigned addr =
                    bSt + (unsigned)(((bRow + p * 16) * GLD) + kk + bK) * 4u;
                ldsm4(bf[2 * p][0], bf[2 * p][1], bf[2 * p + 1][0], bf[2 * p + 1][1], addr);
            }
            if (CVTB) {
#pragma unroll
                for (int ni = 0; ni < 4; ni++) {
                    bf[ni][0] = f2tf(__uint_as_float(bf[ni][0]));
                    bf[ni][1] = f2tf(__uint_as_float(bf[ni][1]));
                }
            }
#pragma unroll
            for (int mi = 0; mi < 4; mi++)
#pragma unroll
                for (int ni = 0; ni < 4; ni++)
                    asm volatile(
                        "mma.sync.aligned.m16n8k8.row.col.f32.tf32.tf32.f32 "
                        "{%0,%1,%2,%3},{%4,%5,%6,%7},{%8,%9},{%0,%1,%2,%3};"
                        : "+f"(acc[mi][ni][0]), "+f"(acc[mi][ni][1]),
                          "+f"(acc[mi][ni][2]), "+f"(acc[mi][ni][3])
                        : "r"(af[mi][0]), "r"(af[mi][1]), "r"(af[mi][2]), "r"(af[mi][3]),
                          "r"(bf[ni][0]), "r"(bf[ni][1]));
        }

        cp_wait2();
        __syncthreads();
    }

    // Epilogue
#pragma unroll
    for (int mi = 0; mi < 4; mi++) {
#pragma unroll
        for (int ni = 0; ni < 4; ni++) {
            const int row = m0 + wm + mi * 16 + g;
            const int col = n0 + wn + ni * 8 + 2 * t4;
            const long long o1 = (long long)row * ldc + col;
            const long long o2 = o1 + (long long)8 * ldc;
            float v0 = alpha * acc[mi][ni][0];
            float v1 = alpha * acc[mi][ni][1];
            float v2 = alpha * acc[mi][ni][2];
            float v3 = alpha * acc[mi][ni][3];
            if (Db) {
                v0 += Db[o1]; v1 += Db[o1 + 1];
                v2 += Db[o2]; v3 += Db[o2 + 1];
            }
            if (ROUNDC) {
                v0 = roundtf(v0); v1 = roundtf(v1);
                v2 = roundtf(v2); v3 = roundtf(v3);
            }
            Cb[o1] = v0; Cb[o1 + 1] = v1;
            Cb[o2] = v2; Cb[o2 + 1] = v3;
        }
    }
}

// ---------------------------------------------------------------------------
// RMSNorm (output rounded to tf32 — consumed only as GEMM A operand)
// ---------------------------------------------------------------------------
__global__ __launch_bounds__(256) void rmsnorm_kernel(
    const float* __restrict__ x, const float* __restrict__ w,
    float* __restrict__ o)
{
    const long long row = blockIdx.x;
    const float* xr = x + row * HIDDEN;
    float* orow = o + row * HIDDEN;

    float ss = 0.f;
    for (int i = threadIdx.x; i < HIDDEN; i += 256) {
        const float v = xr[i];
        ss = fmaf(v, v, ss);
    }
#pragma unroll
    for (int off = 16; off; off >>= 1) ss += __shfl_xor_sync(~0u, ss, off);

    __shared__ float sred[8];
    const int wi = threadIdx.x >> 5, li = threadIdx.x & 31;
    if (li == 0) sred[wi] = ss;
    __syncthreads();
    float tot = 0.f;
#pragma unroll
    for (int i = 0; i < 8; i++) tot += sred[i];

    const float rs = rsqrtf(tot * (1.0f / HIDDEN) + 1e-6f);
    for (int i = threadIdx.x; i < HIDDEN; i += 256)
        orow[i] = roundtf(xr[i] * rs * (1.0f + w[i]));
}

// ---------------------------------------------------------------------------
// RoPE (in place, writes tf32-rounded)
// ---------------------------------------------------------------------------
__global__ void rope_kernel(float* __restrict__ x,
                            const float* __restrict__ cs,
                            const float* __restrict__ sn,
                            int nheads, int tok_stride, long long total)
{
    const long long idx = (long long)blockIdx.x * blockDim.x + threadIdx.x;
    if (idx >= total) return;
    const int i = (int)(idx & 127);
    const long long t = idx >> 7;
    const int h = (int)(t % nheads);
    const long long bs = t / nheads;
    const int s = (int)(bs & (SS - 1));
    const float c = cs[s * 128 + i];
    const float si = sn[s * 128 + i];
    float* p = x + bs * tok_stride + h * HD;
    const float x1 = p[i];
    const float x2 = p[i + 128];
    p[i]       = roundtf(x1 * c - x2 * si);
    p[i + 128] = roundtf(x1 * si + x2 * c);
}

// ---------------------------------------------------------------------------
// Transpose V (writes tf32-rounded)
// ---------------------------------------------------------------------------
__global__ void transpose_v_kernel(const float* __restrict__ v,
                                   float* __restrict__ vt)
{
    __shared__ float tile[32][33];
    const int b = blockIdx.z;
    const int c0 = blockIdx.x * 32;
    const int d0 = blockIdx.y * 32;
    const float* vb = v + (long long)b * SS * QKVN;
    float* vtb = vt + (long long)b * HD * SS;
    const int tx = threadIdx.x, ty = threadIdx.y;
    tile[ty][tx] = vb[(long long)(c0 + ty) * QKVN + d0 + tx];
    __syncthreads();
    vtb[(long long)(d0 + ty) * SS + c0 + tx] = roundtf(tile[tx][ty]);
}

// ---------------------------------------------------------------------------
// Causal softmax (writes tf32-rounded probabilities; zeros masked region)
// ---------------------------------------------------------------------------
__global__ __launch_bounds__(256) void softmax_causal_kernel(float* __restrict__ sc)
{
    const long long rowid = blockIdx.x;
    const int s = (int)(rowid & (SS - 1));
    float* row = sc + rowid * SS;
    const int n = s + 1;

    float mx = -3.4e38f;
    for (int i = threadIdx.x; i < n; i += 256) mx = fmaxf(mx, row[i]);
#pragma unroll
    for (int off = 16; off; off >>= 1) mx = fmaxf(mx, __shfl_xor_sync(~0u, mx, off));

    __shared__ float sm[8], ssum[8];
    const int wi = threadIdx.x >> 5, li = threadIdx.x & 31;
    if (li == 0) sm[wi] = mx;
    __syncthreads();
    float m2 = -3.4e38f;
#pragma unroll
    for (int i = 0; i < 8; i++) m2 = fmaxf(m2, sm[i]);

    float sum = 0.f;
    for (int i = threadIdx.x; i < n; i += 256) sum += __expf(row[i] - m2);
#pragma unroll
    for (int off = 16; off; off >>= 1) sum += __shfl_xor_sync(~0u, sum, off);
    if (li == 0) ssum[wi] = sum;
    __syncthreads();
    float tot = 0.f;
#pragma unroll
    for (int i = 0; i < 8; i++) tot += ssum[i];
    const float inv = 1.0f / tot;

    for (int i = threadIdx.x; i < SS; i += 256)
        row[i] = (i < n) ? roundtf(__expf(row[i] - m2) * inv) : 0.f;
}

// ---------------------------------------------------------------------------
// gate = gelu_tanh(gate) * up (writes tf32-rounded)
// ---------------------------------------------------------------------------
__global__ void gelumul_kernel(float* __restrict__ gate,
                               const float* __restrict__ up,
                               long long total)
{
    const long long i = (long long)blockIdx.x * blockDim.x + threadIdx.x;
    if (i >= total) return;
    const float x = gate[i];
    const float x3 = x * x * x;
    const float t = tanhf(0.7978845608028654f * (x + 0.044715f * x3));
    gate[i] = roundtf(0.5f * x * (1.0f + t) * up[i]);
}

// ---------------------------------------------------------------------------
// Launch
// ---------------------------------------------------------------------------
extern "C" void kernel_launch(void* const* d_in, const int* in_sizes, int n_in,
                              void* d_out, int out_size)
{
    (void)in_sizes; (void)n_in; (void)out_size;

    const float* hidden = (const float*)d_in[0];
    const float* fcos   = (const float*)d_in[1];
    const float* fsin   = (const float*)d_in[2];
    const float* q_w    = (const float*)d_in[7];
    const float* k_w    = (const float*)d_in[8];
    const float* v_w    = (const float*)d_in[9];
    const float* o_w    = (const float*)d_in[10];
    const float* gate_w = (const float*)d_in[11];
    const float* up_w   = (const float*)d_in[12];
    const float* down_w = (const float*)d_in[13];
    const float* ln1    = (const float*)d_in[14];
    const float* ln2    = (const float*)d_in[15];
    float* out = (float*)d_out;

    float *h, *wqkv, *qkv, *vt, *sc, *attn, *h2, *h3, *gbuf, *ubuf;
    cudaGetSymbolAddress((void**)&h,    g_h);
    cudaGetSymbolAddress((void**)&wqkv, g_wqkv);
    cudaGetSymbolAddress((void**)&qkv,  g_qkv);
    cudaGetSymbolAddress((void**)&vt,   g_vt);
    cudaGetSymbolAddress((void**)&sc,   g_sc);
    cudaGetSymbolAddress((void**)&attn, g_attn);
    cudaGetSymbolAddress((void**)&h2,   g_h2);
    cudaGetSymbolAddress((void**)&h3,   g_h3);
    cudaGetSymbolAddress((void**)&gbuf, g_gate);
    cudaGetSymbolAddress((void**)&ubuf, g_up);

    cudaFuncSetAttribute(gemm_tf32_nt<true,  false>,
                         cudaFuncAttributeMaxDynamicSharedMemorySize, GEMM_SMEM);
    cudaFuncSetAttribute(gemm_tf32_nt<false, false>,
                         cudaFuncAttributeMaxDynamicSharedMemorySize, GEMM_SMEM);
    cudaFuncSetAttribute(gemm_tf32_nt<false, true>,
                         cudaFuncAttributeMaxDynamicSharedMemorySize, GEMM_SMEM);

    const float scaling = 0.0625f;   // HEAD_DIM^-0.5 = 1/16

    // 0) concatenate q/k/v weights into one [2560, 2048] matrix
    cudaMemcpyAsync(wqkv,                         q_w, (size_t)KOFF * HIDDEN * 4,
                    cudaMemcpyDeviceToDevice, 0);
    cudaMemcpyAsync(wqkv + (size_t)KOFF * HIDDEN, k_w, (size_t)HD * HIDDEN * 4,
                    cudaMemcpyDeviceToDevice, 0);
    cudaMemcpyAsync(wqkv + (size_t)VOFF * HIDDEN, v_w, (size_t)HD * HIDDEN * 4,
                    cudaMemcpyDeviceToDevice, 0);

    // 1) rmsnorm(hidden, ln1) -> h (tf32-rounded)
    rmsnorm_kernel<<<MTOK, 256>>>(hidden, ln1, h);

    // 2) fused QKV projection
    gemm_tf32_nt<true, false><<<dim3(QKVN / GBN, MTOK / GBM, 1), 256, GEMM_SMEM>>>(
        h, wqkv, qkv, nullptr, HIDDEN, HIDDEN, HIDDEN, QKVN,
        0, 0, 0, 0, 0, 0, 1, 1.0f, 0, 0);

    // 3) RoPE on q and k (rounds in place)
    {
        const long long tq = (long long)MTOK * NH * 128;
        rope_kernel<<<(unsigned)((tq + 255) / 256), 256>>>(
            qkv, fcos, fsin, NH, QKVN, tq);
        const long long tk = (long long)MTOK * 128;
        rope_kernel<<<(unsigned)((tk + 255) / 256), 256>>>(
            qkv + KOFF, fcos, fsin, 1, QKVN, tk);
    }

    // 4) transpose V -> vt (rounds)
    transpose_v_kernel<<<dim3(SS / 32, HD / 32, BB), dim3(32, 32)>>>(
        qkv + VOFF, vt);

    // 5) scores = (q . k^T) * scaling — causal: skip fully-masked blocks
    gemm_tf32_nt<false, false><<<dim3(SS / GBN, SS / GBM, BB * NH), 256, GEMM_SMEM>>>(
        qkv, qkv + KOFF, sc, nullptr, HD,
        QKVN, QKVN, SS,
        (long long)SS * QKVN, (long long)HD,
        (long long)SS * QKVN, 0,
        (long long)NH * SS * SS, (long long)SS * SS,
        NH, scaling, 1, 0);

    // 6) causal softmax (rounds probs, zeros masked cols)
    softmax_causal_kernel<<<BB * NH * SS, 256>>>(sc);

    // 7) attn = probs . v — causal: truncate K to m0+128 (exact, probs=0 beyond)
    gemm_tf32_nt<false, true><<<dim3(HD / GBN, SS / GBM, BB * NH), 256, GEMM_SMEM>>>(
        sc, vt, attn, nullptr, SS,
        SS, SS, NH * HD,
        (long long)NH * SS * SS, (long long)SS * SS,
        (long long)HD * SS, 0,
        (long long)SS * NH * HD, (long long)HD,
        NH, 1.0f, 0, 1);

    // 8) h2 = hidden + attn . o_w^T
    gemm_tf32_nt<true, false><<<dim3(HIDDEN / GBN, MTOK / GBM, 1), 256, GEMM_SMEM>>>(
        attn, o_w, h2, hidden, NH * HD, NH * HD, NH * HD, HIDDEN,
        0, 0, 0, 0, 0, 0, 1, 1.0f, 0, 0);

    // 9) rmsnorm(h2, ln2) -> h3 (rounded)
    rmsnorm_kernel<<<MTOK, 256>>>(h2, ln2, h3);

    // 10-11) gate / up projections
    gemm_tf32_nt<true, false><<<dim3(INTER / GBN, MTOK / GBM, 1), 256, GEMM_SMEM>>>(
        h3, gate_w, gbuf, nullptr, HIDDEN, HIDDEN, HIDDEN, INTER,
        0, 0, 0, 0, 0, 0, 1, 1.0f, 0, 0);
    gemm_tf32_nt<true, false><<<dim3(INTER / GBN, MTOK / GBM, 1), 256, GEMM_SMEM>>>(
        h3, up_w, ubuf, nullptr, HIDDEN, HIDDEN, HIDDEN, INTER,
        0, 0, 0, 0, 0, 0, 1, 1.0f, 0, 0);

    // 12) gbuf = gelu(gbuf) * ubuf (rounded)
    {
        const long long tot = (long long)MTOK * INTER;
        gelumul_kernel<<<(unsigned)((tot + 255) / 256), 256>>>(gbuf, ubuf, tot);
    }

    // 13) out = h2 + gbuf . down_w^T
    gemm_tf32_nt<true, false><<<dim3(HIDDEN / GBN, MTOK / GBM, 1), 256, GEMM_SMEM>>>(
        gbuf, down_w, out, h2, INTER, INTER, INTER, HIDDEN,
        0, 0, 0, 0, 0, 0, 1, 1.0f, 0, 0);
}

// round 14
// speedup vs baseline: 1.2375x; 1.0148x over previous
#include <cuda_runtime.h>
#include <cuda_bf16.h>
#include <cstdint>

// ---------------------------------------------------------------------------
// Problem constants
// ---------------------------------------------------------------------------
#define BB      2
#define SS      2048
#define HIDDEN  2048
#define NH      8
#define NKV     1
#define HD      256
#define INTER   16384
#define MTOK    (BB*SS)          // 4096 tokens
#define QKVN    (NH*HD + 2*HD)   // 2560 fused QKV output cols
#define KOFF    (NH*HD)          // 2048
#define VOFF    (NH*HD + HD)     // 2304

// ---------------------------------------------------------------------------
// Scratch
// ---------------------------------------------------------------------------
__device__ float g_h   [(size_t)MTOK * HIDDEN];
__device__ float g_wqkv[(size_t)QKVN * HIDDEN];
__device__ float g_qkv [(size_t)MTOK * QKVN];
__device__ float g_vt  [(size_t)BB * HD * SS];
__device__ float g_sc  [(size_t)BB * NH * SS * SS];
__device__ float g_attn[(size_t)MTOK * NH * HD];
__device__ float g_h2  [(size_t)MTOK * HIDDEN];
__device__ float g_h3  [(size_t)MTOK * HIDDEN];
__device__ float g_gate[(size_t)MTOK * INTER];
__device__ float g_up  [(size_t)MTOK * INTER];

// ---------------------------------------------------------------------------
// Helpers
// ---------------------------------------------------------------------------
__device__ __forceinline__ unsigned f2tf(float x) {
    unsigned u;
    asm("cvt.rna.tf32.f32 %0, %1;" : "=r"(u) : "f"(x));
    return u;
}
__device__ __forceinline__ float roundtf(float x) {
    return __uint_as_float(f2tf(x));
}
__device__ __forceinline__ void cp_async16(float* sptr, const float* gptr) {
    unsigned sa = (unsigned)__cvta_generic_to_shared(sptr);
    asm volatile("cp.async.cg.shared.global [%0], [%1], 16;\n" :: "r"(sa), "l"(gptr));
}
__device__ __forceinline__ void cp_commit() { asm volatile("cp.async.commit_group;\n"); }
__device__ __forceinline__ void cp_wait1()  { asm volatile("cp.async.wait_group 1;\n"); }
__device__ __forceinline__ void ldsm4(unsigned& r0, unsigned& r1,
                                      unsigned& r2, unsigned& r3, unsigned sa) {
    asm volatile("ldmatrix.sync.aligned.m8n8.x4.shared.b16 {%0,%1,%2,%3}, [%4];"
                 : "=r"(r0), "=r"(r1), "=r"(r2), "=r"(r3) : "r"(sa));
}

// ---------------------------------------------------------------------------
// TF32 NT GEMM: 128x128x32 tiles, 8 warps (64x32 warp tiles), 256 threads,
// 2 CTAs/SM, 3-stage cp.async double-depth pipeline, ldmatrix fragment loads.
// One __syncthreads per 32-K tile (half of R11's boundary count).
// A operands must be pre-rounded to tf32 in gmem.
// CVTB: round B fragments in-loop (raw fp32 weights).
// ROUNDC: round outputs to tf32 (when C feeds a later GEMM as A operand).
// causal_skip: early-return blocks with n0 >= m0+GBM (fully masked scores).
// klim: truncate K loop to m0+GBM (exact for causal probs: zeros beyond).
// ---------------------------------------------------------------------------
#define GBM 128
#define GBN 128
#define GBK 32
#define GLD 36
#define STAGES 3
#define STAGE_F (GBM * GLD)                       // 4608 floats per mat/stage
#define GEMM_SMEM (STAGES * 2 * STAGE_F * 4)      // 110592 bytes

extern __shared__ float g_smem[];

template<bool CVTB, bool ROUNDC>
__global__ __launch_bounds__(256, 2) void gemm_tf32_nt(
    const float* __restrict__ A, const float* __restrict__ B,
    float* __restrict__ C, const float* __restrict__ addsrc,
    int K, int lda, int ldb, int ldc,
    long long sAb, long long sAh,
    long long sBb, long long sBh,
    long long sCb, long long sCh,
    int zInner, float alpha, int causal_skip, int klim)
{
    const int m0  = blockIdx.y * GBM;
    const int n0  = blockIdx.x * GBN;
    if (causal_skip && n0 >= m0 + GBM) return;   // fully-masked scores block

    int Keff = K;
    if (klim && (m0 + GBM) < Keff) Keff = m0 + GBM;  // probs zero beyond row

    float* sA = g_smem;
    float* sB = g_smem + STAGES * STAGE_F;

    const int zb = blockIdx.z / zInner;
    const int zh = blockIdx.z % zInner;
    const float* Ab = A + zb * sAb + zh * sAh;
    const float* Bb = B + zb * sBb + zh * sBh;
    float*       Cb = C + zb * sCb + zh * sCh;
    const float* Db = addsrc ? (addsrc + zb * sCb + zh * sCh) : nullptr;

    const int tid = threadIdx.x;

    // cp.async loaders: 32 floats per row; lr 0..31, rows lr+32*i (i=0..3)
    const int lr = tid >> 3;                  // 0..31
    const int lc = (tid & 7) << 2;            // 0,4,...,28
    const float* Ap0 = Ab + (long long)(m0 + lr) * lda + lc;
    const float* Ap1 = Ab + (long long)(m0 + lr + 32) * lda + lc;
    const float* Ap2 = Ab + (long long)(m0 + lr + 64) * lda + lc;
    const float* Ap3 = Ab + (long long)(m0 + lr + 96) * lda + lc;
    const float* Bp0 = Bb + (long long)(n0 + lr) * ldb + lc;
    const float* Bp1 = Bb + (long long)(n0 + lr + 32) * ldb + lc;
    const float* Bp2 = Bb + (long long)(n0 + lr + 64) * ldb + lc;
    const float* Bp3 = Bb + (long long)(n0 + lr + 96) * ldb + lc;
    const int soff0 = lr * GLD + lc;
    const int soff1 = (lr + 32) * GLD + lc;
    const int soff2 = (lr + 64) * GLD + lc;
    const int soff3 = (lr + 96) * GLD + lc;

    const int lane = tid & 31, warp = tid >> 5;
    const int wm = (warp >> 2) * 64;          // 0 / 64
    const int wn = (warp & 3) * 32;           // 0..96
    const int g  = lane >> 2, t4 = lane & 3;

    // ldmatrix per-lane addressing
    const int aRow = wm + (lane & 15);
    const int aK   = (lane >> 4) << 2;        // 0 or 4
    const int bRow = wn + (lane & 7) + ((lane >> 4) << 3);
    const int bK   = ((lane >> 3) & 1) << 2;  // 0 or 4

    const unsigned sbase  = (unsigned)__cvta_generic_to_shared(g_smem);
    const unsigned sBbase = sbase + (unsigned)(STAGES * STAGE_F) * 4u;

    float acc[4][4][4];
#pragma unroll
    for (int i = 0; i < 4; i++)
#pragma unroll
        for (int j = 0; j < 4; j++)
#pragma unroll
            for (int r = 0; r < 4; r++) acc[i][j][r] = 0.f;

    const int nk = Keff / GBK;

    // Prologue: issue stages 0 and 1
#pragma unroll
    for (int s = 0; s < 2; ++s) {
        if (s < nk) {
            const int ko = s * GBK;
            cp_async16(&sA[s * STAGE_F + soff0], Ap0 + ko);
            cp_async16(&sA[s * STAGE_F + soff1], Ap1 + ko);
            cp_async16(&sA[s * STAGE_F + soff2], Ap2 + ko);
            cp_async16(&sA[s * STAGE_F + soff3], Ap3 + ko);
            cp_async16(&sB[s * STAGE_F + soff0], Bp0 + ko);
            cp_async16(&sB[s * STAGE_F + soff1], Bp1 + ko);
            cp_async16(&sB[s * STAGE_F + soff2], Bp2 + ko);
            cp_async16(&sB[s * STAGE_F + soff3], Bp3 + ko);
        }
        cp_commit();
    }
    cp_wait1();          // stage 0 resident
    __syncthreads();

    for (int t = 0; t < nk; ++t) {
        // Issue stage t+2 (overwrites buffer consumed at t-1; sync at end of
        // iteration t-1 makes that safe)
        const int tf = t + 2;
        if (tf < nk) {
            const int sf = tf % STAGES;
            const int ko = tf * GBK;
            cp_async16(&sA[sf * STAGE_F + soff0], Ap0 + ko);
            cp_async16(&sA[sf * STAGE_F + soff1], Ap1 + ko);
            cp_async16(&sA[sf * STAGE_F + soff2], Ap2 + ko);
            cp_async16(&sA[sf * STAGE_F + soff3], Ap3 + ko);
            cp_async16(&sB[sf * STAGE_F + soff0], Bp0 + ko);
            cp_async16(&sB[sf * STAGE_F + soff1], Bp1 + ko);
            cp_async16(&sB[sf * STAGE_F + soff2], Bp2 + ko);
            cp_async16(&sB[sf * STAGE_F + soff3], Bp3 + ko);
        }
        cp_commit();

        const int s = t % STAGES;
        const unsigned aSt = sbase  + (unsigned)(s * STAGE_F) * 4u;
        const unsigned bSt = sBbase + (unsigned)(s * STAGE_F) * 4u;

#pragma unroll
        for (int kk = 0; kk < GBK; kk += 8) {
            unsigned af[4][4];
            unsigned bf[4][2];
#pragma unroll
            for (int mi = 0; mi < 4; mi++) {
                const unsigned addr =
                    aSt + (unsigned)(((aRow + mi * 16) * GLD) + kk + aK) * 4u;
                ldsm4(af[mi][0], af[mi][1], af[mi][2], af[mi][3], addr);
            }
#pragma unroll
            for (int p = 0; p < 2; p++) {
                const unsigned addr =
                    bSt + (unsigned)(((bRow + p * 16) * GLD) + kk + bK) * 4u;
                ldsm4(bf[2 * p][0], bf[2 * p][1], bf[2 * p + 1][0], bf[2 * p + 1][1], addr);
            }
            if (CVTB) {
#pragma unroll
                for (int ni = 0; ni < 4; ni++) {
                    bf[ni][0] = f2tf(__uint_as_float(bf[ni][0]));
                    bf[ni][1] = f2tf(__uint_as_float(bf[ni][1]));
                }
            }
#pragma unroll
            for (int mi = 0; mi < 4; mi++)
#pragma unroll
                for (int ni = 0; ni < 4; ni++)
                    asm volatile(
                        "mma.sync.aligned.m16n8k8.row.col.f32.tf32.tf32.f32 "
                        "{%0,%1,%2,%3},{%4,%5,%6,%7},{%8,%9},{%0,%1,%2,%3};"
                        : "+f"(acc[mi][ni][0]), "+f"(acc[mi][ni][1]),
                          "+f"(acc[mi][ni][2]), "+f"(acc[mi][ni][3])
                        : "r"(af[mi][0]), "r"(af[mi][1]), "r"(af[mi][2]), "r"(af[mi][3]),
                          "r"(bf[ni][0]), "r"(bf[ni][1]));
        }

        cp_wait1();       // stage t+1 resident for next iteration
        __syncthreads();
    }

    // Epilogue
#pragma unroll
    for (int mi = 0; mi < 4; mi++) {
#pragma unroll
        for (int ni = 0; ni < 4; ni++) {
            const int row = m0 + wm + mi * 16 + g;
            const int col = n0 + wn + ni * 8 + 2 * t4;
            const long long o1 = (long long)row * ldc + col;
            const long long o2 = o1 + (long long)8 * ldc;
            float v0 = alpha * acc[mi][ni][0];
            float v1 = alpha * acc[mi][ni][1];
            float v2 = alpha * acc[mi][ni][2];
            float v3 = alpha * acc[mi][ni][3];
            if (Db) {
                v0 += Db[o1]; v1 += Db[o1 + 1];
                v2 += Db[o2]; v3 += Db[o2 + 1];
            }
            if (ROUNDC) {
                v0 = roundtf(v0); v1 = roundtf(v1);
                v2 = roundtf(v2); v3 = roundtf(v3);
            }
            Cb[o1] = v0; Cb[o1 + 1] = v1;
            Cb[o2] = v2; Cb[o2 + 1] = v3;
        }
    }
}

// ---------------------------------------------------------------------------
// RMSNorm (output rounded to tf32 — consumed only as GEMM A operand)
// ---------------------------------------------------------------------------
__global__ __launch_bounds__(256) void rmsnorm_kernel(
    const float* __restrict__ x, const float* __restrict__ w,
    float* __restrict__ o)
{
    const long long row = blockIdx.x;
    const float* xr = x + row * HIDDEN;
    float* orow = o + row * HIDDEN;

    float ss = 0.f;
    for (int i = threadIdx.x; i < HIDDEN; i += 256) {
        const float v = xr[i];
        ss = fmaf(v, v, ss);
    }
#pragma unroll
    for (int off = 16; off; off >>= 1) ss += __shfl_xor_sync(~0u, ss, off);

    __shared__ float sred[8];
    const int wi = threadIdx.x >> 5, li = threadIdx.x & 31;
    if (li == 0) sred[wi] = ss;
    __syncthreads();
    float tot = 0.f;
#pragma unroll
    for (int i = 0; i < 8; i++) tot += sred[i];

    const float rs = rsqrtf(tot * (1.0f / HIDDEN) + 1e-6f);
    for (int i = threadIdx.x; i < HIDDEN; i += 256)
        orow[i] = roundtf(xr[i] * rs * (1.0f + w[i]));
}

// ---------------------------------------------------------------------------
// RoPE (in place, writes tf32-rounded)
// ---------------------------------------------------------------------------
__global__ void rope_kernel(float* __restrict__ x,
                            const float* __restrict__ cs,
                            const float* __restrict__ sn,
                            int nheads, int tok_stride, long long total)
{
    const long long idx = (long long)blockIdx.x * blockDim.x + threadIdx.x;
    if (idx >= total) return;
    const int i = (int)(idx & 127);
    const long long t = idx >> 7;
    const int h = (int)(t % nheads);
    const long long bs = t / nheads;
    const int s = (int)(bs & (SS - 1));
    const float c = cs[s * 128 + i];
    const float si = sn[s * 128 + i];
    float* p = x + bs * tok_stride + h * HD;
    const float x1 = p[i];
    const float x2 = p[i + 128];
    p[i]       = roundtf(x1 * c - x2 * si);
    p[i + 128] = roundtf(x1 * si + x2 * c);
}

// ---------------------------------------------------------------------------
// Transpose V (writes tf32-rounded)
// ---------------------------------------------------------------------------
__global__ void transpose_v_kernel(const float* __restrict__ v,
                                   float* __restrict__ vt)
{
    __shared__ float tile[32][33];
    const int b = blockIdx.z;
    const int c0 = blockIdx.x * 32;
    const int d0 = blockIdx.y * 32;
    const float* vb = v + (long long)b * SS * QKVN;
    float* vtb = vt + (long long)b * HD * SS;
    const int tx = threadIdx.x, ty = threadIdx.y;
    tile[ty][tx] = vb[(long long)(c0 + ty) * QKVN + d0 + tx];
    __syncthreads();
    vtb[(long long)(d0 + ty) * SS + c0 + tx] = roundtf(tile[tx][ty]);
}

// ---------------------------------------------------------------------------
// Causal softmax. Writes only up to the 128-block boundary containing s:
// PV truncates its K loop to m0+128, so later columns are never read. Exact.
// ---------------------------------------------------------------------------
__global__ __launch_bounds__(256) void softmax_causal_kernel(float* __restrict__ sc)
{
    const long long rowid = blockIdx.x;
    const int s = (int)(rowid & (SS - 1));
    float* row = sc + rowid * SS;
    const int n = s + 1;
    const int lim = ((s >> 7) + 1) << 7;   // next multiple of 128 above s

    float mx = -3.4e38f;
    for (int i = threadIdx.x; i < n; i += 256) mx = fmaxf(mx, row[i]);
#pragma unroll
    for (int off = 16; off; off >>= 1) mx = fmaxf(mx, __shfl_xor_sync(~0u, mx, off));

    __shared__ float sm[8], ssum[8];
    const int wi = threadIdx.x >> 5, li = threadIdx.x & 31;
    if (li == 0) sm[wi] = mx;
    __syncthreads();
    float m2 = -3.4e38f;
#pragma unroll
    for (int i = 0; i < 8; i++) m2 = fmaxf(m2, sm[i]);

    float sum = 0.f;
    for (int i = threadIdx.x; i < n; i += 256) sum += __expf(row[i] - m2);
#pragma unroll
    for (int off = 16; off; off >>= 1) sum += __shfl_xor_sync(~0u, sum, off);
    if (li == 0) ssum[wi] = sum;
    __syncthreads();
    float tot = 0.f;
#pragma unroll
    for (int i = 0; i < 8; i++) tot += ssum[i];
    const float inv = 1.0f / tot;

    for (int i = threadIdx.x; i < lim; i += 256)
        row[i] = (i < n) ? roundtf(__expf(row[i] - m2) * inv) : 0.f;
}

// ---------------------------------------------------------------------------
// gate = gelu_tanh(gate) * up (writes tf32-rounded)
// ---------------------------------------------------------------------------
__global__ void gelumul_kernel(float* __restrict__ gate,
                               const float* __restrict__ up,
                               long long total)
{
    const long long i = (long long)blockIdx.x * blockDim.x + threadIdx.x;
    if (i >= total) return;
    const float x = gate[i];
    const float x3 = x * x * x;
    const float t = tanhf(0.7978845608028654f * (x + 0.044715f * x3));
    gate[i] = roundtf(0.5f * x * (1.0f + t) * up[i]);
}

// ---------------------------------------------------------------------------
// Launch
// ---------------------------------------------------------------------------
extern "C" void kernel_launch(void* const* d_in, const int* in_sizes, int n_in,
                              void* d_out, int out_size)
{
    (void)in_sizes; (void)n_in; (void)out_size;

    const float* hidden = (const float*)d_in[0];
    const float* fcos   = (const float*)d_in[1];
    const float* fsin   = (const float*)d_in[2];
    const float* q_w    = (const float*)d_in[7];
    const float* k_w    = (const float*)d_in[8];
    const float* v_w    = (const float*)d_in[9];
    const float* o_w    = (const float*)d_in[10];
    const float* gate_w = (const float*)d_in[11];
    const float* up_w   = (const float*)d_in[12];
    const float* down_w = (const float*)d_in[13];
    const float* ln1    = (const float*)d_in[14];
    const float* ln2    = (const float*)d_in[15];
    float* out = (float*)d_out;

    float *h, *wqkv, *qkv, *vt, *sc, *attn, *h2, *h3, *gbuf, *ubuf;
    cudaGetSymbolAddress((void**)&h,    g_h);
    cudaGetSymbolAddress((void**)&wqkv, g_wqkv);
    cudaGetSymbolAddress((void**)&qkv,  g_qkv);
    cudaGetSymbolAddress((void**)&vt,   g_vt);
    cudaGetSymbolAddress((void**)&sc,   g_sc);
    cudaGetSymbolAddress((void**)&attn, g_attn);
    cudaGetSymbolAddress((void**)&h2,   g_h2);
    cudaGetSymbolAddress((void**)&h3,   g_h3);
    cudaGetSymbolAddress((void**)&gbuf, g_gate);
    cudaGetSymbolAddress((void**)&ubuf, g_up);

    cudaFuncSetAttribute(gemm_tf32_nt<true,  false>,
                         cudaFuncAttributeMaxDynamicSharedMemorySize, GEMM_SMEM);
    cudaFuncSetAttribute(gemm_tf32_nt<false, false>,
                         cudaFuncAttributeMaxDynamicSharedMemorySize, GEMM_SMEM);
    cudaFuncSetAttribute(gemm_tf32_nt<false, true>,
                         cudaFuncAttributeMaxDynamicSharedMemorySize, GEMM_SMEM);

    const float scaling = 0.0625f;   // HEAD_DIM^-0.5 = 1/16

    // 0) concatenate q/k/v weights into one [2560, 2048] matrix
    cudaMemcpyAsync(wqkv,                         q_w, (size_t)KOFF * HIDDEN * 4,
                    cudaMemcpyDeviceToDevice, 0);
    cudaMemcpyAsync(wqkv + (size_t)KOFF * HIDDEN, k_w, (size_t)HD * HIDDEN * 4,
                    cudaMemcpyDeviceToDevice, 0);
    cudaMemcpyAsync(wqkv + (size_t)VOFF * HIDDEN, v_w, (size_t)HD * HIDDEN * 4,
                    cudaMemcpyDeviceToDevice, 0);

    // 1) rmsnorm(hidden, ln1) -> h (tf32-rounded)
    rmsnorm_kernel<<<MTOK, 256>>>(hidden, ln1, h);

    // 2) fused QKV projection
    gemm_tf32_nt<true, false><<<dim3(QKVN / GBN, MTOK / GBM, 1), 256, GEMM_SMEM>>>(
        h, wqkv, qkv, nullptr, HIDDEN, HIDDEN, HIDDEN, QKVN,
        0, 0, 0, 0, 0, 0, 1, 1.0f, 0, 0);

    // 3) RoPE on q and k (rounds in place)
    {
        const long long tq = (long long)MTOK * NH * 128;
        rope_kernel<<<(unsigned)((tq + 255) / 256), 256>>>(
            qkv, fcos, fsin, NH, QKVN, tq);
        const long long tk = (long long)MTOK * 128;
        rope_kernel<<<(unsigned)((tk + 255) / 256), 256>>>(
            qkv + KOFF, fcos, fsin, 1, QKVN, tk);
    }

    // 4) transpose V -> vt (rounds)
    transpose_v_kernel<<<dim3(SS / 32, HD / 32, BB), dim3(32, 32)>>>(
        qkv + VOFF, vt);

    // 5) scores = (q . k^T) * scaling — causal: skip fully-masked blocks
    gemm_tf32_nt<false, false><<<dim3(SS / GBN, SS / GBM, BB * NH), 256, GEMM_SMEM>>>(
        qkv, qkv + KOFF, sc, nullptr, HD,
        QKVN, QKVN, SS,
        (long long)SS * QKVN, (long long)HD,
        (long long)SS * QKVN, 0,
        (long long)NH * SS * SS, (long long)SS * SS,
        NH, scaling, 1, 0);

    // 6) causal softmax (write-trimmed to 128-block boundary)
    softmax_causal_kernel<<<BB * NH * SS, 256>>>(sc);

    // 7) attn = probs . v — causal: truncate K to m0+128 (exact)
    gemm_tf32_nt<false, true><<<dim3(HD / GBN, SS / GBM, BB * NH), 256, GEMM_SMEM>>>(
        sc, vt, attn, nullptr, SS,
        SS, SS, NH * HD,
        (long long)NH * SS * SS, (long long)SS * SS,
        (long long)HD * SS, 0,
        (long long)SS * NH * HD, (long long)HD,
        NH, 1.0f, 0, 1);

    // 8) h2 = hidden + attn . o_w^T
    gemm_tf32_nt<true, false><<<dim3(HIDDEN / GBN, MTOK / GBM, 1), 256, GEMM_SMEM>>>(
        attn, o_w, h2, hidden, NH * HD, NH * HD, NH * HD, HIDDEN,
        0, 0, 0, 0, 0, 0, 1, 1.0f, 0, 0);

    // 9) rmsnorm(h2, ln2) -> h3 (rounded)
    rmsnorm_kernel<<<MTOK, 256>>>(h2, ln2, h3);

    // 10-11) gate / up projections
    gemm_tf32_nt<true, false><<<dim3(INTER / GBN, MTOK / GBM, 1), 256, GEMM_SMEM>>>(
        h3, gate_w, gbuf, nullptr, HIDDEN, HIDDEN, HIDDEN, INTER,
        0, 0, 0, 0, 0, 0, 1, 1.0f, 0, 0);
    gemm_tf32_nt<true, false><<<dim3(INTER / GBN, MTOK / GBM, 1), 256, GEMM_SMEM>>>(
        h3, up_w, ubuf, nullptr, HIDDEN, HIDDEN, HIDDEN, INTER,
        0, 0, 0, 0, 0, 0, 1, 1.0f, 0, 0);

    // 12) gbuf = gelu(gbuf) * ubuf (rounded)
    {
        const long long tot = (long long)MTOK * INTER;
        gelumul_kernel<<<(unsigned)((tot + 255) / 256), 256>>>(gbuf, ubuf, tot);
    }

    // 13) out = h2 + gbuf . down_w^T
    gemm_tf32_nt<true, false><<<dim3(HIDDEN / GBN, MTOK / GBM, 1), 256, GEMM_SMEM>>>(
        gbuf, down_w, out, h2, INTER, INTER, INTER, HIDDEN,
        0, 0, 0, 0, 0, 0, 1, 1.0f, 0, 0);
}

// round 17
// speedup vs baseline: 1.2747x; 1.0301x over previous
#include <cuda_runtime.h>
#include <cuda_bf16.h>
#include <cstdint>

// ---------------------------------------------------------------------------
// Problem constants
// ---------------------------------------------------------------------------
#define BB      2
#define SS      2048
#define HIDDEN  2048
#define NH      8
#define NKV     1
#define HD      256
#define INTER   16384
#define MTOK    (BB*SS)          // 4096 tokens
#define QKVN    (NH*HD + 2*HD)   // 2560 fused QKV output cols
#define KOFF    (NH*HD)          // 2048
#define VOFF    (NH*HD + HD)     // 2304

// ---------------------------------------------------------------------------
// Scratch
// ---------------------------------------------------------------------------
__device__ float g_h   [(size_t)MTOK * HIDDEN];
__device__ float g_wqkv[(size_t)QKVN * HIDDEN];
__device__ float g_qkv [(size_t)MTOK * QKVN];
__device__ float g_vt  [(size_t)BB * HD * SS];
__device__ float g_sc  [(size_t)BB * NH * SS * SS];
__device__ float g_attn[(size_t)MTOK * NH * HD];
__device__ float g_h2  [(size_t)MTOK * HIDDEN];
__device__ float g_h3  [(size_t)MTOK * HIDDEN];
__device__ float g_gate[(size_t)MTOK * INTER];
__device__ float g_up  [(size_t)MTOK * INTER];   // unused after fusion; kept

// ---------------------------------------------------------------------------
// Helpers
// ---------------------------------------------------------------------------
__device__ __forceinline__ unsigned f2tf(float x) {
    unsigned u;
    asm("cvt.rna.tf32.f32 %0, %1;" : "=r"(u) : "f"(x));
    return u;
}
__device__ __forceinline__ float roundtf(float x) {
    return __uint_as_float(f2tf(x));
}
__device__ __forceinline__ void cp_async16(float* sptr, const float* gptr) {
    unsigned sa = (unsigned)__cvta_generic_to_shared(sptr);
    asm volatile("cp.async.cg.shared.global [%0], [%1], 16;\n" :: "r"(sa), "l"(gptr));
}
__device__ __forceinline__ void cp_commit() { asm volatile("cp.async.commit_group;\n"); }
__device__ __forceinline__ void cp_wait1()  { asm volatile("cp.async.wait_group 1;\n"); }
__device__ __forceinline__ void ldsm4(unsigned& r0, unsigned& r1,
                                      unsigned& r2, unsigned& r3, unsigned sa) {
    asm volatile("ldmatrix.sync.aligned.m8n8.x4.shared.b16 {%0,%1,%2,%3}, [%4];"
                 : "=r"(r0), "=r"(r1), "=r"(r2), "=r"(r3) : "r"(sa));
}

// Exactly matches the standalone gelumul expression/order.
__device__ __forceinline__ float gelu_mul(float x, float up) {
    const float x3 = x * x * x;
    const float t = tanhf(0.7978845608028654f * (x + 0.044715f * x3));
    return roundtf(0.5f * x * (1.0f + t) * up);
}

// ---------------------------------------------------------------------------
// TF32 NT GEMM: 128x128x32 tiles, 8 warps (64x32 warp tiles), 256 threads,
// 2 CTAs/SM, 3-stage cp.async pipeline, ldmatrix fragment loads.
// A operands must be pre-rounded to tf32 in gmem.
// CVTB:   round B fragments in-loop (raw fp32 weights).
// ROUNDC: round outputs to tf32 (when C feeds a later GEMM as A operand).
// GELU:   epilogue computes roundtf(gelu(addsrc[o]) * acc) — fused gelumul.
// causal_skip: early-return blocks with n0 >= m0+GBM (fully masked scores).
// klim: truncate K loop to m0+GBM (exact for causal probs: zeros beyond).
// ---------------------------------------------------------------------------
#define GBM 128
#define GBN 128
#define GBK 32
#define GLD 36
#define STAGES 3
#define STAGE_F (GBM * GLD)                       // 4608 floats per mat/stage
#define GEMM_SMEM (STAGES * 2 * STAGE_F * 4)      // 110592 bytes

extern __shared__ float g_smem[];

template<bool CVTB, bool ROUNDC, bool GELU>
__global__ __launch_bounds__(256, 2) void gemm_tf32_nt(
    const float* __restrict__ A, const float* __restrict__ B,
    float* __restrict__ C, const float* __restrict__ addsrc,
    int K, int lda, int ldb, int ldc,
    long long sAb, long long sAh,
    long long sBb, long long sBh,
    long long sCb, long long sCh,
    int zInner, float alpha, int causal_skip, int klim)
{
    const int m0  = blockIdx.y * GBM;
    const int n0  = blockIdx.x * GBN;
    if (causal_skip && n0 >= m0 + GBM) return;   // fully-masked scores block

    int Keff = K;
    if (klim && (m0 + GBM) < Keff) Keff = m0 + GBM;  // probs zero beyond row

    float* sA = g_smem;
    float* sB = g_smem + STAGES * STAGE_F;

    const int zb = blockIdx.z / zInner;
    const int zh = blockIdx.z % zInner;
    const float* Ab = A + zb * sAb + zh * sAh;
    const float* Bb = B + zb * sBb + zh * sBh;
    float*       Cb = C + zb * sCb + zh * sCh;
    const float* Db = addsrc ? (addsrc + zb * sCb + zh * sCh) : nullptr;

    const int tid = threadIdx.x;

    // cp.async loaders: 32 floats per row; lr 0..31, rows lr+32*i (i=0..3)
    const int lr = tid >> 3;                  // 0..31
    const int lc = (tid & 7) << 2;            // 0,4,...,28
    const float* Ap0 = Ab + (long long)(m0 + lr) * lda + lc;
    const float* Ap1 = Ab + (long long)(m0 + lr + 32) * lda + lc;
    const float* Ap2 = Ab + (long long)(m0 + lr + 64) * lda + lc;
    const float* Ap3 = Ab + (long long)(m0 + lr + 96) * lda + lc;
    const float* Bp0 = Bb + (long long)(n0 + lr) * ldb + lc;
    const float* Bp1 = Bb + (long long)(n0 + lr + 32) * ldb + lc;
    const float* Bp2 = Bb + (long long)(n0 + lr + 64) * ldb + lc;
    const float* Bp3 = Bb + (long long)(n0 + lr + 96) * ldb + lc;
    const int soff0 = lr * GLD + lc;
    const int soff1 = (lr + 32) * GLD + lc;
    const int soff2 = (lr + 64) * GLD + lc;
    const int soff3 = (lr + 96) * GLD + lc;

    const int lane = tid & 31, warp = tid >> 5;
    const int wm = (warp >> 2) * 64;          // 0 / 64
    const int wn = (warp & 3) * 32;           // 0..96
    const int g  = lane >> 2, t4 = lane & 3;

    // ldmatrix per-lane addressing
    const int aRow = wm + (lane & 15);
    const int aK   = (lane >> 4) << 2;        // 0 or 4
    const int bRow = wn + (lane & 7) + ((lane >> 4) << 3);
    const int bK   = ((lane >> 3) & 1) << 2;  // 0 or 4

    const unsigned sbase  = (unsigned)__cvta_generic_to_shared(g_smem);
    const unsigned sBbase = sbase + (unsigned)(STAGES * STAGE_F) * 4u;

    float acc[4][4][4];
#pragma unroll
    for (int i = 0; i < 4; i++)
#pragma unroll
        for (int j = 0; j < 4; j++)
#pragma unroll
            for (int r = 0; r < 4; r++) acc[i][j][r] = 0.f;

    const int nk = Keff / GBK;

    // Prologue: issue stages 0 and 1
#pragma unroll
    for (int s = 0; s < 2; ++s) {
        if (s < nk) {
            const int ko = s * GBK;
            cp_async16(&sA[s * STAGE_F + soff0], Ap0 + ko);
            cp_async16(&sA[s * STAGE_F + soff1], Ap1 + ko);
            cp_async16(&sA[s * STAGE_F + soff2], Ap2 + ko);
            cp_async16(&sA[s * STAGE_F + soff3], Ap3 + ko);
            cp_async16(&sB[s * STAGE_F + soff0], Bp0 + ko);
            cp_async16(&sB[s * STAGE_F + soff1], Bp1 + ko);
            cp_async16(&sB[s * STAGE_F + soff2], Bp2 + ko);
            cp_async16(&sB[s * STAGE_F + soff3], Bp3 + ko);
        }
        cp_commit();
    }
    cp_wait1();          // stage 0 resident
    __syncthreads();

    for (int t = 0; t < nk; ++t) {
        const int tf = t + 2;
        if (tf < nk) {
            const int sf = tf % STAGES;
            const int ko = tf * GBK;
            cp_async16(&sA[sf * STAGE_F + soff0], Ap0 + ko);
            cp_async16(&sA[sf * STAGE_F + soff1], Ap1 + ko);
            cp_async16(&sA[sf * STAGE_F + soff2], Ap2 + ko);
            cp_async16(&sA[sf * STAGE_F + soff3], Ap3 + ko);
            cp_async16(&sB[sf * STAGE_F + soff0], Bp0 + ko);
            cp_async16(&sB[sf * STAGE_F + soff1], Bp1 + ko);
            cp_async16(&sB[sf * STAGE_F + soff2], Bp2 + ko);
            cp_async16(&sB[sf * STAGE_F + soff3], Bp3 + ko);
        }
        cp_commit();

        const int s = t % STAGES;
        const unsigned aSt = sbase  + (unsigned)(s * STAGE_F) * 4u;
        const unsigned bSt = sBbase + (unsigned)(s * STAGE_F) * 4u;

#pragma unroll
        for (int kk = 0; kk < GBK; kk += 8) {
            unsigned af[4][4];
            unsigned bf[4][2];
#pragma unroll
            for (int mi = 0; mi < 4; mi++) {
                const unsigned addr =
                    aSt + (unsigned)(((aRow + mi * 16) * GLD) + kk + aK) * 4u;
                ldsm4(af[mi][0], af[mi][1], af[mi][2], af[mi][3], addr);
            }
#pragma unroll
            for (int p = 0; p < 2; p++) {
                const unsigned addr =
                    bSt + (unsigned)(((bRow + p * 16) * GLD) + kk + bK) * 4u;
                ldsm4(bf[2 * p][0], bf[2 * p][1], bf[2 * p + 1][0], bf[2 * p + 1][1], addr);
            }
            if (CVTB) {
#pragma unroll
                for (int ni = 0; ni < 4; ni++) {
                    bf[ni][0] = f2tf(__uint_as_float(bf[ni][0]));
                    bf[ni][1] = f2tf(__uint_as_float(bf[ni][1]));
                }
            }
#pragma unroll
            for (int mi = 0; mi < 4; mi++)
#pragma unroll
                for (int ni = 0; ni < 4; ni++)
                    asm volatile(
                        "mma.sync.aligned.m16n8k8.row.col.f32.tf32.tf32.f32 "
                        "{%0,%1,%2,%3},{%4,%5,%6,%7},{%8,%9},{%0,%1,%2,%3};"
                        : "+f"(acc[mi][ni][0]), "+f"(acc[mi][ni][1]),
                          "+f"(acc[mi][ni][2]), "+f"(acc[mi][ni][3])
                        : "r"(af[mi][0]), "r"(af[mi][1]), "r"(af[mi][2]), "r"(af[mi][3]),
                          "r"(bf[ni][0]), "r"(bf[ni][1]));
        }

        cp_wait1();       // stage t+1 resident for next iteration
        __syncthreads();
    }

    // Epilogue
#pragma unroll
    for (int mi = 0; mi < 4; mi++) {
#pragma unroll
        for (int ni = 0; ni < 4; ni++) {
            const int row = m0 + wm + mi * 16 + g;
            const int col = n0 + wn + ni * 8 + 2 * t4;
            const long long o1 = (long long)row * ldc + col;
            const long long o2 = o1 + (long long)8 * ldc;
            float v0 = alpha * acc[mi][ni][0];
            float v1 = alpha * acc[mi][ni][1];
            float v2 = alpha * acc[mi][ni][2];
            float v3 = alpha * acc[mi][ni][3];
            if (GELU) {
                // acc = up value; addsrc = gate value. Same math/order as the
                // standalone gelumul kernel (bit-identical).
                v0 = gelu_mul(Db[o1],     v0);
                v1 = gelu_mul(Db[o1 + 1], v1);
                v2 = gelu_mul(Db[o2],     v2);
                v3 = gelu_mul(Db[o2 + 1], v3);
            } else {
                if (Db) {
                    v0 += Db[o1]; v1 += Db[o1 + 1];
                    v2 += Db[o2]; v3 += Db[o2 + 1];
                }
                if (ROUNDC) {
                    v0 = roundtf(v0); v1 = roundtf(v1);
                    v2 = roundtf(v2); v3 = roundtf(v3);
                }
            }
            Cb[o1] = v0; Cb[o1 + 1] = v1;
            Cb[o2] = v2; Cb[o2 + 1] = v3;
        }
    }
}

// ---------------------------------------------------------------------------
// RMSNorm (output rounded to tf32 — consumed only as GEMM A operand)
// ---------------------------------------------------------------------------
__global__ __launch_bounds__(256) void rmsnorm_kernel(
    const float* __restrict__ x, const float* __restrict__ w,
    float* __restrict__ o)
{
    const long long row = blockIdx.x;
    const float* xr = x + row * HIDDEN;
    float* orow = o + row * HIDDEN;

    float ss = 0.f;
    for (int i = threadIdx.x; i < HIDDEN; i += 256) {
        const float v = xr[i];
        ss = fmaf(v, v, ss);
    }
#pragma unroll
    for (int off = 16; off; off >>= 1) ss += __shfl_xor_sync(~0u, ss, off);

    __shared__ float sred[8];
    const int wi = threadIdx.x >> 5, li = threadIdx.x & 31;
    if (li == 0) sred[wi] = ss;
    __syncthreads();
    float tot = 0.f;
#pragma unroll
    for (int i = 0; i < 8; i++) tot += sred[i];

    const float rs = rsqrtf(tot * (1.0f / HIDDEN) + 1e-6f);
    for (int i = threadIdx.x; i < HIDDEN; i += 256)
        orow[i] = roundtf(xr[i] * rs * (1.0f + w[i]));
}

// ---------------------------------------------------------------------------
// RoPE (in place, writes tf32-rounded)
// ---------------------------------------------------------------------------
__global__ void rope_kernel(float* __restrict__ x,
                            const float* __restrict__ cs,
                            const float* __restrict__ sn,
                            int nheads, int tok_stride, long long total)
{
    const long long idx = (long long)blockIdx.x * blockDim.x + threadIdx.x;
    if (idx >= total) return;
    const int i = (int)(idx & 127);
    const long long t = idx >> 7;
    const int h = (int)(t % nheads);
    const long long bs = t / nheads;
    const int s = (int)(bs & (SS - 1));
    const float c = cs[s * 128 + i];
    const float si = sn[s * 128 + i];
    float* p = x + bs * tok_stride + h * HD;
    const float x1 = p[i];
    const float x2 = p[i + 128];
    p[i]       = roundtf(x1 * c - x2 * si);
    p[i + 128] = roundtf(x1 * si + x2 * c);
}

// ---------------------------------------------------------------------------
// Transpose V (writes tf32-rounded)
// ---------------------------------------------------------------------------
__global__ void transpose_v_kernel(const float* __restrict__ v,
                                   float* __restrict__ vt)
{
    __shared__ float tile[32][33];
    const int b = blockIdx.z;
    const int c0 = blockIdx.x * 32;
    const int d0 = blockIdx.y * 32;
    const float* vb = v + (long long)b * SS * QKVN;
    float* vtb = vt + (long long)b * HD * SS;
    const int tx = threadIdx.x, ty = threadIdx.y;
    tile[ty][tx] = vb[(long long)(c0 + ty) * QKVN + d0 + tx];
    __syncthreads();
    vtb[(long long)(d0 + ty) * SS + c0 + tx] = roundtf(tile[tx][ty]);
}

// ---------------------------------------------------------------------------
// Causal softmax. Writes only up to the 128-block boundary containing s:
// PV truncates its K loop to m0+128, so later columns are never read. Exact.
// ---------------------------------------------------------------------------
__global__ __launch_bounds__(256) void softmax_causal_kernel(float* __restrict__ sc)
{
    const long long rowid = blockIdx.x;
    const int s = (int)(rowid & (SS - 1));
    float* row = sc + rowid * SS;
    const int n = s + 1;
    const int lim = ((s >> 7) + 1) << 7;   // next multiple of 128 above s

    float mx = -3.4e38f;
    for (int i = threadIdx.x; i < n; i += 256) mx = fmaxf(mx, row[i]);
#pragma unroll
    for (int off = 16; off; off >>= 1) mx = fmaxf(mx, __shfl_xor_sync(~0u, mx, off));

    __shared__ float sm[8], ssum[8];
    const int wi = threadIdx.x >> 5, li = threadIdx.x & 31;
    if (li == 0) sm[wi] = mx;
    __syncthreads();
    float m2 = -3.4e38f;
#pragma unroll
    for (int i = 0; i < 8; i++) m2 = fmaxf(m2, sm[i]);

    float sum = 0.f;
    for (int i = threadIdx.x; i < n; i += 256) sum += __expf(row[i] - m2);
#pragma unroll
    for (int off = 16; off; off >>= 1) sum += __shfl_xor_sync(~0u, sum, off);
    if (li == 0) ssum[wi] = sum;
    __syncthreads();
    float tot = 0.f;
#pragma unroll
    for (int i = 0; i < 8; i++) tot += ssum[i];
    const float inv = 1.0f / tot;

    for (int i = threadIdx.x; i < lim; i += 256)
        row[i] = (i < n) ? roundtf(__expf(row[i] - m2) * inv) : 0.f;
}

// ---------------------------------------------------------------------------
// Launch
// ---------------------------------------------------------------------------
extern "C" void kernel_launch(void* const* d_in, const int* in_sizes, int n_in,
                              void* d_out, int out_size)
{
    (void)in_sizes; (void)n_in; (void)out_size;

    const float* hidden = (const float*)d_in[0];
    const float* fcos   = (const float*)d_in[1];
    const float* fsin   = (const float*)d_in[2];
    const float* q_w    = (const float*)d_in[7];
    const float* k_w    = (const float*)d_in[8];
    const float* v_w    = (const float*)d_in[9];
    const float* o_w    = (const float*)d_in[10];
    const float* gate_w = (const float*)d_in[11];
    const float* up_w   = (const float*)d_in[12];
    const float* down_w = (const float*)d_in[13];
    const float* ln1    = (const float*)d_in[14];
    const float* ln2    = (const float*)d_in[15];
    float* out = (float*)d_out;

    float *h, *wqkv, *qkv, *vt, *sc, *attn, *h2, *h3, *gbuf;
    cudaGetSymbolAddress((void**)&h,    g_h);
    cudaGetSymbolAddress((void**)&wqkv, g_wqkv);
    cudaGetSymbolAddress((void**)&qkv,  g_qkv);
    cudaGetSymbolAddress((void**)&vt,   g_vt);
    cudaGetSymbolAddress((void**)&sc,   g_sc);
    cudaGetSymbolAddress((void**)&attn, g_attn);
    cudaGetSymbolAddress((void**)&h2,   g_h2);
    cudaGetSymbolAddress((void**)&h3,   g_h3);
    cudaGetSymbolAddress((void**)&gbuf, g_gate);

    cudaFuncSetAttribute(gemm_tf32_nt<true,  false, false>,
                         cudaFuncAttributeMaxDynamicSharedMemorySize, GEMM_SMEM);
    cudaFuncSetAttribute(gemm_tf32_nt<false, false, false>,
                         cudaFuncAttributeMaxDynamicSharedMemorySize, GEMM_SMEM);
    cudaFuncSetAttribute(gemm_tf32_nt<false, true,  false>,
                         cudaFuncAttributeMaxDynamicSharedMemorySize, GEMM_SMEM);
    cudaFuncSetAttribute(gemm_tf32_nt<true,  false, true>,
                         cudaFuncAttributeMaxDynamicSharedMemorySize, GEMM_SMEM);

    const float scaling = 0.0625f;   // HEAD_DIM^-0.5 = 1/16

    // 0) concatenate q/k/v weights into one [2560, 2048] matrix
    cudaMemcpyAsync(wqkv,                         q_w, (size_t)KOFF * HIDDEN * 4,
                    cudaMemcpyDeviceToDevice, 0);
    cudaMemcpyAsync(wqkv + (size_t)KOFF * HIDDEN, k_w, (size_t)HD * HIDDEN * 4,
                    cudaMemcpyDeviceToDevice, 0);
    cudaMemcpyAsync(wqkv + (size_t)VOFF * HIDDEN, v_w, (size_t)HD * HIDDEN * 4,
                    cudaMemcpyDeviceToDevice, 0);

    // 1) rmsnorm(hidden, ln1) -> h (tf32-rounded)
    rmsnorm_kernel<<<MTOK, 256>>>(hidden, ln1, h);

    // 2) fused QKV projection
    gemm_tf32_nt<true, false, false><<<dim3(QKVN / GBN, MTOK / GBM, 1), 256, GEMM_SMEM>>>(
        h, wqkv, qkv, nullptr, HIDDEN, HIDDEN, HIDDEN, QKVN,
        0, 0, 0, 0, 0, 0, 1, 1.0f, 0, 0);

    // 3) RoPE on q and k (rounds in place)
    {
        const long long tq = (long long)MTOK * NH * 128;
        rope_kernel<<<(unsigned)((tq + 255) / 256), 256>>>(
            qkv, fcos, fsin, NH, QKVN, tq);
        const long long tk = (long long)MTOK * 128;
        rope_kernel<<<(unsigned)((tk + 255) / 256), 256>>>(
            qkv + KOFF, fcos, fsin, 1, QKVN, tk);
    }

    // 4) transpose V -> vt (rounds)
    transpose_v_kernel<<<dim3(SS / 32, HD / 32, BB), dim3(32, 32)>>>(
        qkv + VOFF, vt);

    // 5) scores = (q . k^T) * scaling — causal: skip fully-masked blocks
    gemm_tf32_nt<false, false, false><<<dim3(SS / GBN, SS / GBM, BB * NH), 256, GEMM_SMEM>>>(
        qkv, qkv + KOFF, sc, nullptr, HD,
        QKVN, QKVN, SS,
        (long long)SS * QKVN, (long long)HD,
        (long long)SS * QKVN, 0,
        (long long)NH * SS * SS, (long long)SS * SS,
        NH, scaling, 1, 0);

    // 6) causal softmax (write-trimmed to 128-block boundary)
    softmax_causal_kernel<<<BB * NH * SS, 256>>>(sc);

    // 7) attn = probs . v — causal: truncate K to m0+128 (exact)
    gemm_tf32_nt<false, true, false><<<dim3(HD / GBN, SS / GBM, BB * NH), 256, GEMM_SMEM>>>(
        sc, vt, attn, nullptr, SS,
        SS, SS, NH * HD,
        (long long)NH * SS * SS, (long long)SS * SS,
        (long long)HD * SS, 0,
        (long long)SS * NH * HD, (long long)HD,
        NH, 1.0f, 0, 1);

    // 8) h2 = hidden + attn . o_w^T
    gemm_tf32_nt<true, false, false><<<dim3(HIDDEN / GBN, MTOK / GBM, 1), 256, GEMM_SMEM>>>(
        attn, o_w, h2, hidden, NH * HD, NH * HD, NH * HD, HIDDEN,
        0, 0, 0, 0, 0, 0, 1, 1.0f, 0, 0);

    // 9) rmsnorm(h2, ln2) -> h3 (rounded)
    rmsnorm_kernel<<<MTOK, 256>>>(h2, ln2, h3);

    // 10) gate projection -> gbuf (raw fp32)
    gemm_tf32_nt<true, false, false><<<dim3(INTER / GBN, MTOK / GBM, 1), 256, GEMM_SMEM>>>(
        h3, gate_w, gbuf, nullptr, HIDDEN, HIDDEN, HIDDEN, INTER,
        0, 0, 0, 0, 0, 0, 1, 1.0f, 0, 0);

    // 11) up projection with FUSED gelumul epilogue:
    //     gbuf = roundtf(gelu(gbuf) * up)   (bit-identical to the old
    //     separate gelumul pass; saves ~800 MB of HBM traffic)
    gemm_tf32_nt<true, false, true><<<dim3(INTER / GBN, MTOK / GBM, 1), 256, GEMM_SMEM>>>(
        h3, up_w, gbuf, gbuf, HIDDEN, HIDDEN, HIDDEN, INTER,
        0, 0, 0, 0, 0, 0, 1, 1.0f, 0, 0);

    // 12) out = h2 + gbuf . down_w^T
    gemm_tf32_nt<true, false, false><<<dim3(HIDDEN / GBN, MTOK / GBM, 1), 256, GEMM_SMEM>>>(
        gbuf, down_w, out, h2, INTER, INTER, INTER, HIDDEN,
        0, 0, 0, 0, 0, 0, 1, 1.0f, 0, 0);
}